// round 2
// baseline (speedup 1.0000x reference)
#include <cuda_runtime.h>
#include <math.h>

#define B_  32
#define J_  1024
#define D_  192
#define E_  384
#define N_  16
#define R_  (B_ * J_)          // 32768 rows
#define RE_ (R_ * E_)          // 12,582,912

// ---------------- scratch ----------------------------------------------------
__device__ float g_t[R_ * D_];          // LayerNorm output
__device__ float g_x[R_ * E_];          // x = t@Wx + bx
__device__ float g_gate[R_ * E_];       // sigmoid(silu(z))
__device__ float g_bcdu[B_ * 128 * J_]; // [b][c][j]; c 0-63 fwd {B,C,D,u}, 64-127 bwd
__device__ float g_S[R_ * N_];          // S_f + flip(S_b), (B,J,N)
__device__ float g_y[R_ * E_];          // gated readout

__device__ __forceinline__ float softplusf(float x) {
    return (x > 20.f) ? x : log1pf(expf(x));
}
__device__ __forceinline__ float sigmoidf_(float x) {
    return 1.f / (1.f + expf(-x));
}

// ---------------- K1: LayerNorm (warp per row, D=192 = 6*32) ------------------
__global__ void ln_kernel(const float* __restrict__ tokens,
                          const float* __restrict__ g,
                          const float* __restrict__ b) {
    int warp = (blockIdx.x * blockDim.x + threadIdx.x) >> 5;
    int lane = threadIdx.x & 31;
    if (warp >= R_) return;
    const float* row = tokens + warp * D_;
    float v[6];
    float sum = 0.f;
#pragma unroll
    for (int i = 0; i < 6; i++) { v[i] = row[lane + i * 32]; sum += v[i]; }
#pragma unroll
    for (int o = 16; o; o >>= 1) sum += __shfl_xor_sync(0xffffffffu, sum, o);
    float mu = sum * (1.f / D_);
    float sq = 0.f;
#pragma unroll
    for (int i = 0; i < 6; i++) { float d = v[i] - mu; sq += d * d; }
#pragma unroll
    for (int o = 16; o; o >>= 1) sq += __shfl_xor_sync(0xffffffffu, sq, o);
    float inv = rsqrtf(sq * (1.f / D_) + 1e-5f);
    float* out = g_t + warp * D_;
#pragma unroll
    for (int i = 0; i < 6; i++) {
        int c = lane + i * 32;
        out[c] = (v[i] - mu) * inv * g[c] + b[c];
    }
}

// ---------------- K2: GEMM t @ [Wx|Wz]  (M=32768, N=768, K=192) ---------------
// 128x64 tile, 256 threads, 8x4 microtile.
__global__ void gemm_xz_kernel(const float* __restrict__ Wx,
                               const float* __restrict__ bx,
                               const float* __restrict__ Wz,
                               const float* __restrict__ bz) {
    const int BM = 128, BN = 64, BK = 16;
    __shared__ float As[BK][BM + 1];
    __shared__ float Bs[BK][BN];
    int bm = blockIdx.y * BM;
    int bn = blockIdx.x * BN;
    int tid = threadIdx.x;
    int tx = tid & 15, ty = tid >> 4;   // rows ty*8.., cols tx*4..
    float acc[8][4] = {};
    for (int k0 = 0; k0 < D_; k0 += BK) {
#pragma unroll
        for (int i = tid; i < BM * BK; i += 256) {
            int m = i >> 4, k = i & 15;
            As[k][m] = g_t[(bm + m) * D_ + k0 + k];
        }
#pragma unroll
        for (int i = tid; i < BK * BN; i += 256) {
            int k = i >> 6, c = i & 63;
            int gc = bn + c;
            Bs[k][c] = (gc < E_) ? Wx[(k0 + k) * E_ + gc]
                                 : Wz[(k0 + k) * E_ + gc - E_];
        }
        __syncthreads();
#pragma unroll
        for (int k = 0; k < BK; k++) {
            float a[8], bb[4];
#pragma unroll
            for (int i = 0; i < 8; i++) a[i]  = As[k][ty * 8 + i];
#pragma unroll
            for (int j = 0; j < 4; j++) bb[j] = Bs[k][tx * 4 + j];
#pragma unroll
            for (int i = 0; i < 8; i++)
#pragma unroll
                for (int j = 0; j < 4; j++) acc[i][j] += a[i] * bb[j];
        }
        __syncthreads();
    }
#pragma unroll
    for (int i = 0; i < 8; i++) {
        int row = bm + ty * 8 + i;
#pragma unroll
        for (int j = 0; j < 4; j++) {
            int gc = bn + tx * 4 + j;
            float v = acc[i][j];
            if (gc < E_) {
                g_x[row * E_ + gc] = v + bx[gc];
            } else {
                int e = gc - E_;
                float z = v + bz[e];
                float s = z * sigmoidf_(z);
                g_gate[row * E_ + e] = sigmoidf_(s);
            }
        }
    }
}

// ---------------- K3: fused depthwise-conv (both dirs) + projections ----------
// One block per 64 rows of one batch. For each K-chunk: load x halo tile,
// compute xc_f and xc_b in smem, accumulate both 64x64 GEMMs
// [WB|WC|WD|Wi]. Write to g_bcdu transposed; bwd written at flipped step.
__global__ void convproj_kernel(
    const float* __restrict__ cwf, const float* __restrict__ cbf,
    const float* __restrict__ cwb, const float* __restrict__ cbb,
    const float* __restrict__ WBf, const float* __restrict__ bBf,
    const float* __restrict__ WCf, const float* __restrict__ bCf,
    const float* __restrict__ WDf, const float* __restrict__ bDf,
    const float* __restrict__ WBb, const float* __restrict__ bBb,
    const float* __restrict__ WCb, const float* __restrict__ bCb,
    const float* __restrict__ WDb, const float* __restrict__ bDb,
    const float* __restrict__ Wi,  const float* __restrict__ bi) {
    const int BK = 32;
    __shared__ float Xs[66][33];        // rows j0-1 .. j0+64, chunk cols
    __shared__ float Af[BK][65];        // xc_f chunk, k-major
    __shared__ float Ab[BK][65];        // xc_b chunk, k-major
    __shared__ float Bf[BK][64];
    __shared__ float Bb[BK][64];

    const float* Wpf[4] = {WBf, WCf, WDf, Wi};
    const float* Wpb[4] = {WBb, WCb, WDb, Wi};

    int bid = blockIdx.x;
    int b = bid >> 4;
    int j0 = (bid & 15) * 64;
    int tid = threadIdx.x;
    int tx = tid & 15, ty = tid >> 4;

    float accf[4][4] = {};
    float accb[4][4] = {};

    for (int k0 = 0; k0 < E_; k0 += BK) {
        // load x tile with halo (zero outside batch)
        for (int i = tid; i < 66 * 32; i += 256) {
            int rr = i >> 5, cc = i & 31;
            int j = j0 - 1 + rr;
            Xs[rr][cc] = (j >= 0 && j < J_)
                       ? g_x[(b * J_ + j) * E_ + k0 + cc] : 0.f;
        }
        // load weight chunks
        for (int i = tid; i < BK * 64; i += 256) {
            int k = i >> 6, c = i & 63;
            Bf[k][c] = Wpf[c >> 4][(k0 + k) * N_ + (c & 15)];
            Bb[k][c] = Wpb[c >> 4][(k0 + k) * N_ + (c & 15)];
        }
        __syncthreads();
        // conv: out row j = j0+r -> x[j-1]=Xs[r], x[j]=Xs[r+1], x[j+1]=Xs[r+2]
        for (int i = tid; i < 64 * 32; i += 256) {
            int r = i >> 5, cc = i & 31;
            int e = k0 + cc;
            float xm = Xs[r][cc], x0 = Xs[r + 1][cc], xp = Xs[r + 2][cc];
            Af[cc][r] = cbf[e] + cwf[e * 3 + 0] * xm + cwf[e * 3 + 1] * x0
                                + cwf[e * 3 + 2] * xp;
            // bwd conv at step s=1023-j: taps hit x[j+1],x[j],x[j-1]
            Ab[cc][r] = cbb[e] + cwb[e * 3 + 0] * xp + cwb[e * 3 + 1] * x0
                                + cwb[e * 3 + 2] * xm;
        }
        __syncthreads();
#pragma unroll
        for (int k = 0; k < BK; k++) {
            float af[4], ab[4], bf[4], bb[4];
#pragma unroll
            for (int i = 0; i < 4; i++) { af[i] = Af[k][ty * 4 + i];
                                          ab[i] = Ab[k][ty * 4 + i]; }
#pragma unroll
            for (int j = 0; j < 4; j++) { bf[j] = Bf[k][tx * 4 + j];
                                          bb[j] = Bb[k][tx * 4 + j]; }
#pragma unroll
            for (int i = 0; i < 4; i++)
#pragma unroll
                for (int j = 0; j < 4; j++) {
                    accf[i][j] += af[i] * bf[j];
                    accb[i][j] += ab[i] * bb[j];
                }
        }
        __syncthreads();
    }
    const float* bpf[4] = {bBf, bCf, bDf, bi};
    const float* bpb[4] = {bBb, bCb, bDb, bi};
#pragma unroll
    for (int i = 0; i < 4; i++) {
        int j  = j0 + ty * 4 + i;
        int jb = J_ - 1 - j;
#pragma unroll
        for (int jj = 0; jj < 4; jj++) {
            int c = tx * 4 + jj;
            float vf = accf[i][jj] + bpf[c >> 4][c & 15];
            float vb = accb[i][jj] + bpb[c >> 4][c & 15];
            g_bcdu[(b * 128 + c) * J_ + j] = vf;
            g_bcdu[(b * 128 + 64 + c) * J_ + jb] = vb;
        }
    }
}

// ---------------- K4: fused bidirectional selective scan ----------------------
// One block per (b,n). Forward scan, then backward scan, summed in smem.
__global__ void scan2_kernel(const float* __restrict__ A_log) {
    int b = blockIdx.x >> 4;
    int n = blockIdx.x & 15;
    int t = threadIdx.x;
    float An = -softplusf(A_log[n]);
    float inv_den = 1.f / (An + 1e-6f);
    const float* base = g_bcdu + b * 128 * J_;

    __shared__ float sAcc[J_];
    __shared__ float sP[128], sS[128];

#pragma unroll
    for (int dir = 0; dir < 2; dir++) {
        int co = dir * 64;
        const float* Bt = base + (co + n) * J_;
        const float* Ct = base + (co + 16 + n) * J_;
        const float* Dr = base + (co + 32 + n) * J_;
        const float* Ut = base + (co + 48 + n) * J_;

        int j0 = t * 8;
        float hl[8], pp[8], cc[8];
        float P = 1.f, S = 0.f;
#pragma unroll
        for (int i = 0; i < 8; i++) {
            int j = j0 + i;
            float dt = softplusf(Dr[j]);
            float ab = expf(dt * An);
            float bu = (ab - 1.f) * inv_den * Bt[j] * Ut[j];
            S = ab * S + bu;
            P = P * ab;
            hl[i] = S; pp[i] = P; cc[i] = Ct[j];
        }
        float iP = P, iS = S;
        for (int off = 1; off < 128; off <<= 1) {
            sP[t] = iP; sS[t] = iS;
            __syncthreads();
            if (t >= off) {
                float qP = sP[t - off], qS = sS[t - off];
                iS = qS * iP + iS;
                iP = qP * iP;
            }
            __syncthreads();
        }
        sS[t] = iS;
        __syncthreads();
        float Hin = (t == 0) ? 0.f : sS[t - 1];
        __syncthreads();   // ensure all reads of sS done before sAcc phase reuse

#pragma unroll
        for (int i = 0; i < 8; i++) {
            int j = j0 + i;
            float h = hl[i] + pp[i] * Hin;
            float sc = h * cc[i];
            if (dir == 0) sAcc[j] = sc;
            else          sAcc[J_ - 1 - j] += sc;
        }
        __syncthreads();
    }

#pragma unroll
    for (int i = 0; i < 8; i++) {
        int pos = t * 8 + i;
        g_S[(b * J_ + pos) * N_ + n] = sAcc[pos];
    }
}

// ---------------- K5: readout (K=16 dot) + 2*br + gate ------------------------
__global__ void readout_kernel(const float* __restrict__ Wr,
                               const float* __restrict__ br) {
    int idx = blockIdx.x * blockDim.x + threadIdx.x;
    if (idx >= RE_) return;
    int e = idx % E_;
    int r = idx / E_;
    const float* s = g_S + r * N_;
    float acc = 0.f;
#pragma unroll
    for (int n = 0; n < N_; n++) acc += s[n] * Wr[n * E_ + e];
    g_y[idx] = (acc + 2.f * br[e]) * g_gate[idx];
}

// ---------------- K6: output GEMM y @ Wo + bo + tokens ------------------------
__global__ void gemm_out_kernel(const float* __restrict__ Wo,
                                const float* __restrict__ bo,
                                const float* __restrict__ tokens,
                                float* __restrict__ out) {
    const int BM = 128, BN = 64, BK = 16;
    __shared__ float As[BK][BM + 1];
    __shared__ float Bs[BK][BN];
    int bm = blockIdx.y * BM;
    int bn = blockIdx.x * BN;
    int tid = threadIdx.x;
    int tx = tid & 15, ty = tid >> 4;
    float acc[8][4] = {};
    for (int k0 = 0; k0 < E_; k0 += BK) {
#pragma unroll
        for (int i = tid; i < BM * BK; i += 256) {
            int m = i >> 4, k = i & 15;
            As[k][m] = g_y[(bm + m) * E_ + k0 + k];
        }
#pragma unroll
        for (int i = tid; i < BK * BN; i += 256) {
            int k = i >> 6, c = i & 63;
            Bs[k][c] = Wo[(k0 + k) * D_ + bn + c];
        }
        __syncthreads();
#pragma unroll
        for (int k = 0; k < BK; k++) {
            float a[8], bb[4];
#pragma unroll
            for (int i = 0; i < 8; i++) a[i]  = As[k][ty * 8 + i];
#pragma unroll
            for (int j = 0; j < 4; j++) bb[j] = Bs[k][tx * 4 + j];
#pragma unroll
            for (int i = 0; i < 8; i++)
#pragma unroll
                for (int j = 0; j < 4; j++) acc[i][j] += a[i] * bb[j];
        }
        __syncthreads();
    }
#pragma unroll
    for (int i = 0; i < 8; i++) {
        int row = bm + ty * 8 + i;
#pragma unroll
        for (int j = 0; j < 4; j++) {
            int gc = bn + tx * 4 + j;
            out[row * D_ + gc] = tokens[row * D_ + gc] + acc[i][j] + bo[gc];
        }
    }
}

// ---------------- launcher ----------------------------------------------------
extern "C" void kernel_launch(void* const* d_in, const int* in_sizes, int n_in,
                              void* d_out, int out_size) {
    const float* tokens  = (const float*)d_in[0];
    const float* norm_g  = (const float*)d_in[1];
    const float* norm_b  = (const float*)d_in[2];
    const float* Wx      = (const float*)d_in[3];
    const float* bx      = (const float*)d_in[4];
    const float* Wz      = (const float*)d_in[5];
    const float* bz      = (const float*)d_in[6];
    const float* convf_w = (const float*)d_in[7];
    const float* convf_b = (const float*)d_in[8];
    const float* convb_w = (const float*)d_in[9];
    const float* convb_b = (const float*)d_in[10];
    const float* WBf = (const float*)d_in[11];
    const float* bBf = (const float*)d_in[12];
    const float* WCf = (const float*)d_in[13];
    const float* bCf = (const float*)d_in[14];
    const float* WDf = (const float*)d_in[15];
    const float* bDf = (const float*)d_in[16];
    const float* WBb = (const float*)d_in[17];
    const float* bBb = (const float*)d_in[18];
    const float* WCb = (const float*)d_in[19];
    const float* bCb = (const float*)d_in[20];
    const float* WDb = (const float*)d_in[21];
    const float* bDb = (const float*)d_in[22];
    const float* A_log = (const float*)d_in[23];
    const float* Wi  = (const float*)d_in[24];
    const float* bi  = (const float*)d_in[25];
    const float* Wr  = (const float*)d_in[26];
    const float* br  = (const float*)d_in[27];
    const float* Wo  = (const float*)d_in[28];
    const float* bo  = (const float*)d_in[29];
    float* out = (float*)d_out;

    ln_kernel<<<R_ / 8, 256>>>(tokens, norm_g, norm_b);

    gemm_xz_kernel<<<dim3(12, R_ / 128), 256>>>(Wx, bx, Wz, bz);

    convproj_kernel<<<512, 256>>>(convf_w, convf_b, convb_w, convb_b,
                                  WBf, bBf, WCf, bCf, WDf, bDf,
                                  WBb, bBb, WCb, bCb, WDb, bDb, Wi, bi);

    scan2_kernel<<<B_ * N_, 128>>>(A_log);

    readout_kernel<<<RE_ / 256, 256>>>(Wr, br);

    gemm_out_kernel<<<dim3(3, R_ / 128), 256>>>(Wo, bo, tokens, out);
}

// round 3
// speedup vs baseline: 1.9423x; 1.9423x over previous
#include <cuda_runtime.h>
#include <cuda_bf16.h>
#include <math.h>
#include <stdint.h>

#define B_  32
#define J_  1024
#define D_  192
#define E_  384
#define N_  16
#define R_  (B_ * J_)          // 32768 rows
#define RE_ (R_ * E_)          // 12,582,912

// ---------------- scratch ----------------------------------------------------
__device__ __nv_bfloat16 g_tb[R_ * D_];     // LayerNorm output (bf16)
__device__ float g_x[R_ * E_];              // x = t@Wx + bx
__device__ float g_gate[R_ * E_];           // sigmoid(silu(z))
__device__ float g_bcdu[B_ * 128 * J_];     // [b][c][j]; 0-63 fwd {B,C,D,u}, 64-127 bwd
__device__ float g_S[R_ * N_];              // S_f + flip(S_b)
__device__ __nv_bfloat16 g_yb[R_ * E_];     // gated readout (bf16)
__device__ __nv_bfloat16 g_wxz[D_ * 2 * E_]; // [192][768] packed Wx|Wz bf16
__device__ __nv_bfloat16 g_wo[E_ * D_];      // [384][192] Wo bf16

__device__ __forceinline__ float softplusf(float x) {
    return (x > 20.f) ? x : log1pf(expf(x));
}
__device__ __forceinline__ float sigmoidf_(float x) {
    return 1.f / (1.f + expf(-x));
}

// ---------------- tensor-core primitives --------------------------------------
__device__ __forceinline__ uint32_t smem_u32(const void* p) {
    return (uint32_t)__cvta_generic_to_shared(p);
}
__device__ __forceinline__ void ldsm_x4(uint32_t& r0, uint32_t& r1,
                                        uint32_t& r2, uint32_t& r3, uint32_t a) {
    asm volatile("ldmatrix.sync.aligned.m8n8.x4.shared.b16 {%0,%1,%2,%3}, [%4];"
                 : "=r"(r0), "=r"(r1), "=r"(r2), "=r"(r3) : "r"(a));
}
__device__ __forceinline__ void ldsm_x4_t(uint32_t& r0, uint32_t& r1,
                                          uint32_t& r2, uint32_t& r3, uint32_t a) {
    asm volatile("ldmatrix.sync.aligned.m8n8.x4.trans.shared.b16 {%0,%1,%2,%3}, [%4];"
                 : "=r"(r0), "=r"(r1), "=r"(r2), "=r"(r3) : "r"(a));
}
__device__ __forceinline__ void mma16816(float* d, const uint32_t* a,
                                         uint32_t b0, uint32_t b1) {
    asm volatile(
        "mma.sync.aligned.m16n8k16.row.col.f32.bf16.bf16.f32 "
        "{%0,%1,%2,%3}, {%4,%5,%6,%7}, {%8,%9}, {%0,%1,%2,%3};"
        : "+f"(d[0]), "+f"(d[1]), "+f"(d[2]), "+f"(d[3])
        : "r"(a[0]), "r"(a[1]), "r"(a[2]), "r"(a[3]), "r"(b0), "r"(b1));
}

// ---------------- K0: weight conversion to bf16 -------------------------------
__global__ void wcvt_kernel(const float* __restrict__ Wx, const float* __restrict__ Wz,
                            const float* __restrict__ Wo) {
    int i = blockIdx.x * blockDim.x + threadIdx.x;
    int nxz = D_ * 2 * E_;            // 147456
    int nwo = E_ * D_;                // 73728
    if (i < nxz) {
        int k = i / (2 * E_), c = i % (2 * E_);
        float v = (c < E_) ? Wx[k * E_ + c] : Wz[k * E_ + c - E_];
        g_wxz[i] = __float2bfloat16_rn(v);
    } else if (i < nxz + nwo) {
        int j = i - nxz;
        g_wo[j] = __float2bfloat16_rn(Wo[j]);
    }
}

// ---------------- K1: LayerNorm -> bf16 ---------------------------------------
__global__ void ln_kernel(const float* __restrict__ tokens,
                          const float* __restrict__ g,
                          const float* __restrict__ b) {
    int warp = (blockIdx.x * blockDim.x + threadIdx.x) >> 5;
    int lane = threadIdx.x & 31;
    if (warp >= R_) return;
    const float* row = tokens + warp * D_;
    float v[6];
    float sum = 0.f;
#pragma unroll
    for (int i = 0; i < 6; i++) { v[i] = row[lane + i * 32]; sum += v[i]; }
#pragma unroll
    for (int o = 16; o; o >>= 1) sum += __shfl_xor_sync(0xffffffffu, sum, o);
    float mu = sum * (1.f / D_);
    float sq = 0.f;
#pragma unroll
    for (int i = 0; i < 6; i++) { float d = v[i] - mu; sq += d * d; }
#pragma unroll
    for (int o = 16; o; o >>= 1) sq += __shfl_xor_sync(0xffffffffu, sq, o);
    float inv = rsqrtf(sq * (1.f / D_) + 1e-5f);
    __nv_bfloat16* out = g_tb + warp * D_;
#pragma unroll
    for (int i = 0; i < 6; i++) {
        int c = lane + i * 32;
        out[c] = __float2bfloat16_rn((v[i] - mu) * inv * g[c] + b[c]);
    }
}

// ---------------- K2: TC GEMM t @ [Wx|Wz] -------------------------------------
// BM=128, BN=64, BK=32. 8 warps (4x2), warp tile 32x32.
#define AP 40   // A smem row stride (bf16)
#define BP 72   // B smem row stride (bf16)
__global__ void gemm_xz_tc(const float* __restrict__ bx,
                           const float* __restrict__ bz) {
    __shared__ __align__(16) __nv_bfloat16 As[128 * AP];
    __shared__ __align__(16) __nv_bfloat16 Bs[32 * BP];
    int bm = blockIdx.y * 128;
    int bn = blockIdx.x * 64;
    int tid = threadIdx.x;
    int w = tid >> 5, lane = tid & 31;
    int wm = (w >> 1) * 32, wn = (w & 1) * 32;

    float acc[2][4][4] = {};

    for (int k0 = 0; k0 < D_; k0 += 32) {
        // load A: 128 rows x 32 cols bf16, 16B per thread-load, 2 iters
#pragma unroll
        for (int it = 0; it < 2; it++) {
            int idx = tid + it * 256;
            int r = idx >> 2, seg = idx & 3;
            *(uint4*)&As[r * AP + seg * 8] =
                *(const uint4*)&g_tb[(bm + r) * D_ + k0 + seg * 8];
        }
        // load B: 32 rows x 64 cols
        {
            int r = tid >> 3, seg = tid & 7;
            *(uint4*)&Bs[r * BP + seg * 8] =
                *(const uint4*)&g_wxz[(k0 + r) * (2 * E_) + bn + seg * 8];
        }
        __syncthreads();
#pragma unroll
        for (int kk = 0; kk < 2; kk++) {
            uint32_t a[2][4], bfr[2][4];
#pragma unroll
            for (int i = 0; i < 2; i++) {
                uint32_t ad = smem_u32(&As[(wm + i * 16 + (lane & 15)) * AP
                                           + kk * 16 + (lane >> 4) * 8]);
                ldsm_x4(a[i][0], a[i][1], a[i][2], a[i][3], ad);
            }
#pragma unroll
            for (int jp = 0; jp < 2; jp++) {
                int krow = kk * 16 + (lane & 7) + ((lane >> 3) & 1) * 8;
                uint32_t bd = smem_u32(&Bs[krow * BP + wn + jp * 16
                                           + (lane >> 4) * 8]);
                ldsm_x4_t(bfr[jp][0], bfr[jp][1], bfr[jp][2], bfr[jp][3], bd);
            }
#pragma unroll
            for (int i = 0; i < 2; i++) {
#pragma unroll
                for (int jp = 0; jp < 2; jp++) {
                    mma16816(acc[i][jp * 2 + 0], a[i], bfr[jp][0], bfr[jp][1]);
                    mma16816(acc[i][jp * 2 + 1], a[i], bfr[jp][2], bfr[jp][3]);
                }
            }
        }
        __syncthreads();
    }

    int gq = lane >> 2, tq = lane & 3;
    bool isx = (bn < E_);
#pragma unroll
    for (int i = 0; i < 2; i++) {
#pragma unroll
        for (int jj = 0; jj < 4; jj++) {
#pragma unroll
            for (int h = 0; h < 2; h++) {     // row halves
                int r = bm + wm + i * 16 + gq + h * 8;
#pragma unroll
                for (int q = 0; q < 2; q++) { // col pair
                    int c = bn + wn + jj * 8 + tq * 2 + q;
                    float v = acc[i][jj][h * 2 + q];
                    if (isx) {
                        g_x[r * E_ + c] = v + bx[c];
                    } else {
                        int e = c - E_;
                        float z = v + bz[e];
                        float s = z * sigmoidf_(z);
                        g_gate[r * E_ + e] = sigmoidf_(s);
                    }
                }
            }
        }
    }
}

// ---------------- K3: fused conv (both dirs) + projections --------------------
__global__ void convproj_kernel(
    const float* __restrict__ cwf, const float* __restrict__ cbf,
    const float* __restrict__ cwb, const float* __restrict__ cbb,
    const float* __restrict__ WBf, const float* __restrict__ bBf,
    const float* __restrict__ WCf, const float* __restrict__ bCf,
    const float* __restrict__ WDf, const float* __restrict__ bDf,
    const float* __restrict__ WBb, const float* __restrict__ bBb,
    const float* __restrict__ WCb, const float* __restrict__ bCb,
    const float* __restrict__ WDb, const float* __restrict__ bDb,
    const float* __restrict__ Wi,  const float* __restrict__ bi) {
    const int BK = 32;
    __shared__ float Xs[66][33];
    __shared__ float Af[BK][65];
    __shared__ float Ab[BK][65];
    __shared__ float Bf[BK][64];
    __shared__ float Bb[BK][64];

    const float* Wpf[4] = {WBf, WCf, WDf, Wi};
    const float* Wpb[4] = {WBb, WCb, WDb, Wi};

    int bid = blockIdx.x;
    int b = bid >> 4;
    int j0 = (bid & 15) * 64;
    int tid = threadIdx.x;
    int tx = tid & 15, ty = tid >> 4;

    float accf[4][4] = {};
    float accb[4][4] = {};

    for (int k0 = 0; k0 < E_; k0 += BK) {
        for (int i = tid; i < 66 * 32; i += 256) {
            int rr = i >> 5, cc = i & 31;
            int j = j0 - 1 + rr;
            Xs[rr][cc] = (j >= 0 && j < J_)
                       ? g_x[(b * J_ + j) * E_ + k0 + cc] : 0.f;
        }
        for (int i = tid; i < BK * 64; i += 256) {
            int k = i >> 6, c = i & 63;
            Bf[k][c] = Wpf[c >> 4][(k0 + k) * N_ + (c & 15)];
            Bb[k][c] = Wpb[c >> 4][(k0 + k) * N_ + (c & 15)];
        }
        __syncthreads();
        for (int i = tid; i < 64 * 32; i += 256) {
            int r = i >> 5, cc = i & 31;
            int e = k0 + cc;
            float xm = Xs[r][cc], x0 = Xs[r + 1][cc], xp = Xs[r + 2][cc];
            Af[cc][r] = cbf[e] + cwf[e * 3 + 0] * xm + cwf[e * 3 + 1] * x0
                                + cwf[e * 3 + 2] * xp;
            Ab[cc][r] = cbb[e] + cwb[e * 3 + 0] * xp + cwb[e * 3 + 1] * x0
                                + cwb[e * 3 + 2] * xm;
        }
        __syncthreads();
#pragma unroll
        for (int k = 0; k < BK; k++) {
            float af[4], ab[4], bf[4], bb[4];
#pragma unroll
            for (int i = 0; i < 4; i++) { af[i] = Af[k][ty * 4 + i];
                                          ab[i] = Ab[k][ty * 4 + i]; }
#pragma unroll
            for (int j = 0; j < 4; j++) { bf[j] = Bf[k][tx * 4 + j];
                                          bb[j] = Bb[k][tx * 4 + j]; }
#pragma unroll
            for (int i = 0; i < 4; i++)
#pragma unroll
                for (int j = 0; j < 4; j++) {
                    accf[i][j] += af[i] * bf[j];
                    accb[i][j] += ab[i] * bb[j];
                }
        }
        __syncthreads();
    }
    const float* bpf[4] = {bBf, bCf, bDf, bi};
    const float* bpb[4] = {bBb, bCb, bDb, bi};
#pragma unroll
    for (int i = 0; i < 4; i++) {
        int j  = j0 + ty * 4 + i;
        int jb = J_ - 1 - j;
#pragma unroll
        for (int jj = 0; jj < 4; jj++) {
            int c = tx * 4 + jj;
            float vf = accf[i][jj] + bpf[c >> 4][c & 15];
            float vb = accb[i][jj] + bpb[c >> 4][c & 15];
            g_bcdu[(b * 128 + c) * J_ + j] = vf;
            g_bcdu[(b * 128 + 64 + c) * J_ + jb] = vb;
        }
    }
}

// ---------------- K4: fused bidirectional selective scan ----------------------
__global__ void scan2_kernel(const float* __restrict__ A_log) {
    int b = blockIdx.x >> 4;
    int n = blockIdx.x & 15;
    int t = threadIdx.x;
    float An = -softplusf(A_log[n]);
    float inv_den = 1.f / (An + 1e-6f);
    const float* base = g_bcdu + b * 128 * J_;

    __shared__ float sAcc[J_];
    __shared__ float sP[128], sS[128];

#pragma unroll
    for (int dir = 0; dir < 2; dir++) {
        int co = dir * 64;
        const float* Bt = base + (co + n) * J_;
        const float* Ct = base + (co + 16 + n) * J_;
        const float* Dr = base + (co + 32 + n) * J_;
        const float* Ut = base + (co + 48 + n) * J_;

        int j0 = t * 8;
        float hl[8], pp[8], cc[8];
        float P = 1.f, S = 0.f;
#pragma unroll
        for (int i = 0; i < 8; i++) {
            int j = j0 + i;
            float dt = softplusf(Dr[j]);
            float ab = expf(dt * An);
            float bu = (ab - 1.f) * inv_den * Bt[j] * Ut[j];
            S = ab * S + bu;
            P = P * ab;
            hl[i] = S; pp[i] = P; cc[i] = Ct[j];
        }
        float iP = P, iS = S;
        for (int off = 1; off < 128; off <<= 1) {
            sP[t] = iP; sS[t] = iS;
            __syncthreads();
            if (t >= off) {
                float qP = sP[t - off], qS = sS[t - off];
                iS = qS * iP + iS;
                iP = qP * iP;
            }
            __syncthreads();
        }
        sS[t] = iS;
        __syncthreads();
        float Hin = (t == 0) ? 0.f : sS[t - 1];
        __syncthreads();

#pragma unroll
        for (int i = 0; i < 8; i++) {
            int j = j0 + i;
            float h = hl[i] + pp[i] * Hin;
            float sc = h * cc[i];
            if (dir == 0) sAcc[j] = sc;
            else          sAcc[J_ - 1 - j] += sc;
        }
        __syncthreads();
    }

#pragma unroll
    for (int i = 0; i < 8; i++) {
        int pos = t * 8 + i;
        g_S[(b * J_ + pos) * N_ + n] = sAcc[pos];
    }
}

// ---------------- K5: readout + gate -> bf16 ----------------------------------
__global__ void readout_kernel(const float* __restrict__ Wr,
                               const float* __restrict__ br) {
    int idx = blockIdx.x * blockDim.x + threadIdx.x;
    if (idx >= RE_) return;
    int e = idx % E_;
    int r = idx / E_;
    const float* s = g_S + r * N_;
    float acc = 0.f;
#pragma unroll
    for (int n = 0; n < N_; n++) acc += s[n] * Wr[n * E_ + e];
    g_yb[idx] = __float2bfloat16_rn((acc + 2.f * br[e]) * g_gate[idx]);
}

// ---------------- K6: TC GEMM y @ Wo + residual -------------------------------
__global__ void gemm_out_tc(const float* __restrict__ bo,
                            const float* __restrict__ tokens,
                            float* __restrict__ out) {
    __shared__ __align__(16) __nv_bfloat16 As[128 * AP];
    __shared__ __align__(16) __nv_bfloat16 Bs[32 * BP];
    int bm = blockIdx.y * 128;
    int bn = blockIdx.x * 64;
    int tid = threadIdx.x;
    int w = tid >> 5, lane = tid & 31;
    int wm = (w >> 1) * 32, wn = (w & 1) * 32;

    float acc[2][4][4] = {};

    for (int k0 = 0; k0 < E_; k0 += 32) {
#pragma unroll
        for (int it = 0; it < 2; it++) {
            int idx = tid + it * 256;
            int r = idx >> 2, seg = idx & 3;
            *(uint4*)&As[r * AP + seg * 8] =
                *(const uint4*)&g_yb[(bm + r) * E_ + k0 + seg * 8];
        }
        {
            int r = tid >> 3, seg = tid & 7;
            *(uint4*)&Bs[r * BP + seg * 8] =
                *(const uint4*)&g_wo[(k0 + r) * D_ + bn + seg * 8];
        }
        __syncthreads();
#pragma unroll
        for (int kk = 0; kk < 2; kk++) {
            uint32_t a[2][4], bfr[2][4];
#pragma unroll
            for (int i = 0; i < 2; i++) {
                uint32_t ad = smem_u32(&As[(wm + i * 16 + (lane & 15)) * AP
                                           + kk * 16 + (lane >> 4) * 8]);
                ldsm_x4(a[i][0], a[i][1], a[i][2], a[i][3], ad);
            }
#pragma unroll
            for (int jp = 0; jp < 2; jp++) {
                int krow = kk * 16 + (lane & 7) + ((lane >> 3) & 1) * 8;
                uint32_t bd = smem_u32(&Bs[krow * BP + wn + jp * 16
                                           + (lane >> 4) * 8]);
                ldsm_x4_t(bfr[jp][0], bfr[jp][1], bfr[jp][2], bfr[jp][3], bd);
            }
#pragma unroll
            for (int i = 0; i < 2; i++) {
#pragma unroll
                for (int jp = 0; jp < 2; jp++) {
                    mma16816(acc[i][jp * 2 + 0], a[i], bfr[jp][0], bfr[jp][1]);
                    mma16816(acc[i][jp * 2 + 1], a[i], bfr[jp][2], bfr[jp][3]);
                }
            }
        }
        __syncthreads();
    }

    int gq = lane >> 2, tq = lane & 3;
#pragma unroll
    for (int i = 0; i < 2; i++) {
#pragma unroll
        for (int jj = 0; jj < 4; jj++) {
#pragma unroll
            for (int h = 0; h < 2; h++) {
                int r = bm + wm + i * 16 + gq + h * 8;
#pragma unroll
                for (int q = 0; q < 2; q++) {
                    int c = bn + wn + jj * 8 + tq * 2 + q;
                    out[r * D_ + c] = tokens[r * D_ + c]
                                    + acc[i][jj][h * 2 + q] + bo[c];
                }
            }
        }
    }
}

// ---------------- launcher ----------------------------------------------------
extern "C" void kernel_launch(void* const* d_in, const int* in_sizes, int n_in,
                              void* d_out, int out_size) {
    const float* tokens  = (const float*)d_in[0];
    const float* norm_g  = (const float*)d_in[1];
    const float* norm_b  = (const float*)d_in[2];
    const float* Wx      = (const float*)d_in[3];
    const float* bx      = (const float*)d_in[4];
    const float* Wz      = (const float*)d_in[5];
    const float* bz      = (const float*)d_in[6];
    const float* convf_w = (const float*)d_in[7];
    const float* convf_b = (const float*)d_in[8];
    const float* convb_w = (const float*)d_in[9];
    const float* convb_b = (const float*)d_in[10];
    const float* WBf = (const float*)d_in[11];
    const float* bBf = (const float*)d_in[12];
    const float* WCf = (const float*)d_in[13];
    const float* bCf = (const float*)d_in[14];
    const float* WDf = (const float*)d_in[15];
    const float* bDf = (const float*)d_in[16];
    const float* WBb = (const float*)d_in[17];
    const float* bBb = (const float*)d_in[18];
    const float* WCb = (const float*)d_in[19];
    const float* bCb = (const float*)d_in[20];
    const float* WDb = (const float*)d_in[21];
    const float* bDb = (const float*)d_in[22];
    const float* A_log = (const float*)d_in[23];
    const float* Wi  = (const float*)d_in[24];
    const float* bi  = (const float*)d_in[25];
    const float* Wr  = (const float*)d_in[26];
    const float* br  = (const float*)d_in[27];
    const float* Wo  = (const float*)d_in[28];
    const float* bo  = (const float*)d_in[29];
    float* out = (float*)d_out;

    wcvt_kernel<<<(D_ * 2 * E_ + E_ * D_ + 255) / 256, 256>>>(Wx, Wz, Wo);
    ln_kernel<<<R_ / 8, 256>>>(tokens, norm_g, norm_b);

    gemm_xz_tc<<<dim3(12, R_ / 128), 256>>>(bx, bz);

    convproj_kernel<<<512, 256>>>(convf_w, convf_b, convb_w, convb_b,
                                  WBf, bBf, WCf, bCf, WDf, bDf,
                                  WBb, bBb, WCb, bCb, WDb, bDb, Wi, bi);

    scan2_kernel<<<B_ * N_, 128>>>(A_log);

    readout_kernel<<<RE_ / 256, 256>>>(Wr, br);

    gemm_out_tc<<<dim3(3, R_ / 128), 256>>>(bo, tokens, out);
}

// round 5
// speedup vs baseline: 3.1582x; 1.6260x over previous
#include <cuda_runtime.h>
#include <cuda_bf16.h>
#include <math.h>
#include <stdint.h>

#define B_  32
#define J_  1024
#define D_  192
#define E_  384
#define N_  16
#define R_  (B_ * J_)          // 32768 rows
#define RE_ (R_ * E_)          // 12,582,912

// ---------------- scratch ----------------------------------------------------
__device__ __nv_bfloat16 g_tb[R_ * D_];      // LayerNorm output (bf16)
__device__ float g_x[R_ * E_];               // x = t@Wx + bx (fp32 for conv accuracy)
__device__ __nv_bfloat16 g_gateb[R_ * E_];   // sigmoid(silu(z)) bf16
__device__ __nv_bfloat16 g_xcf[R_ * E_];     // fwd conv out bf16
__device__ __nv_bfloat16 g_xcb[R_ * E_];     // bwd conv out bf16 (indexed by j)
__device__ float g_bcdu[B_ * 128 * J_];      // [b][c][j]; 0-63 fwd {B,C,D,u}, 64-127 bwd
__device__ float g_S[R_ * N_];               // S_f + flip(S_b)
__device__ __nv_bfloat16 g_yb[R_ * E_];      // gated readout (bf16)
__device__ __nv_bfloat16 g_wxz[D_ * 2 * E_]; // [192][768] packed Wx|Wz bf16
__device__ __nv_bfloat16 g_wo[E_ * D_];      // [384][192] Wo bf16
__device__ __nv_bfloat16 g_wp[2 * E_ * 64];  // per-dir packed [WB|WC|WD|Wi] bf16
__device__ float g_bp[2 * 64];               // per-dir packed biases

__device__ __forceinline__ float softplusf(float x) {
    return (x > 20.f) ? x : log1pf(expf(x));
}
__device__ __forceinline__ float sigmoidf_(float x) {
    return 1.f / (1.f + expf(-x));
}

// ---------------- tensor-core primitives --------------------------------------
__device__ __forceinline__ uint32_t smem_u32(const void* p) {
    return (uint32_t)__cvta_generic_to_shared(p);
}
__device__ __forceinline__ void ldsm_x4(uint32_t& r0, uint32_t& r1,
                                        uint32_t& r2, uint32_t& r3, uint32_t a) {
    asm volatile("ldmatrix.sync.aligned.m8n8.x4.shared.b16 {%0,%1,%2,%3}, [%4];"
                 : "=r"(r0), "=r"(r1), "=r"(r2), "=r"(r3) : "r"(a));
}
__device__ __forceinline__ void ldsm_x4_t(uint32_t& r0, uint32_t& r1,
                                          uint32_t& r2, uint32_t& r3, uint32_t a) {
    asm volatile("ldmatrix.sync.aligned.m8n8.x4.trans.shared.b16 {%0,%1,%2,%3}, [%4];"
                 : "=r"(r0), "=r"(r1), "=r"(r2), "=r"(r3) : "r"(a));
}
__device__ __forceinline__ void mma16816(float* d, const uint32_t* a,
                                         uint32_t b0, uint32_t b1) {
    asm volatile(
        "mma.sync.aligned.m16n8k16.row.col.f32.bf16.bf16.f32 "
        "{%0,%1,%2,%3}, {%4,%5,%6,%7}, {%8,%9}, {%0,%1,%2,%3};"
        : "+f"(d[0]), "+f"(d[1]), "+f"(d[2]), "+f"(d[3])
        : "r"(a[0]), "r"(a[1]), "r"(a[2]), "r"(a[3]), "r"(b0), "r"(b1));
}

#define AP 40   // A smem row stride (bf16)
#define BP 72   // B smem row stride (bf16)

// ---------------- K0: weight conversion / packing -----------------------------
__global__ void wcvt_kernel(const float* __restrict__ Wx, const float* __restrict__ Wz,
                            const float* __restrict__ Wo,
                            const float* __restrict__ WBf, const float* __restrict__ WCf,
                            const float* __restrict__ WDf,
                            const float* __restrict__ WBb, const float* __restrict__ WCb,
                            const float* __restrict__ WDb,
                            const float* __restrict__ Wi,
                            const float* __restrict__ bBf, const float* __restrict__ bCf,
                            const float* __restrict__ bDf,
                            const float* __restrict__ bBb, const float* __restrict__ bCb,
                            const float* __restrict__ bDb,
                            const float* __restrict__ bi) {
    const int nxz = D_ * 2 * E_;            // 147456
    const int nwo = E_ * D_;                // 73728
    const int nwp = 2 * E_ * 64;            // 49152
    int i = blockIdx.x * blockDim.x + threadIdx.x;
    if (i < nxz) {
        int k = i / (2 * E_), c = i % (2 * E_);
        float v = (c < E_) ? Wx[k * E_ + c] : Wz[k * E_ + c - E_];
        g_wxz[i] = __float2bfloat16_rn(v);
    } else if (i < nxz + nwo) {
        int j = i - nxz;
        g_wo[j] = __float2bfloat16_rn(Wo[j]);
    } else if (i < nxz + nwo + nwp) {
        int j = i - nxz - nwo;
        int dir = j / (E_ * 64);
        int rem = j % (E_ * 64);
        int k = rem / 64, c = rem % 64;
        const float* W;
        int p = c >> 4;
        if (p == 3) W = Wi;
        else if (dir == 0) W = (p == 0) ? WBf : (p == 1) ? WCf : WDf;
        else               W = (p == 0) ? WBb : (p == 1) ? WCb : WDb;
        g_wp[j] = __float2bfloat16_rn(W[k * N_ + (c & 15)]);
    } else if (i < nxz + nwo + nwp + 128) {
        int j = i - nxz - nwo - nwp;
        int dir = j >> 6, c = j & 63;
        int p = c >> 4;
        const float* bb;
        if (p == 3) bb = bi;
        else if (dir == 0) bb = (p == 0) ? bBf : (p == 1) ? bCf : bDf;
        else               bb = (p == 0) ? bBb : (p == 1) ? bCb : bDb;
        g_bp[j] = bb[c & 15];
    }
}

// ---------------- K1: LayerNorm -> bf16 ---------------------------------------
__global__ void ln_kernel(const float* __restrict__ tokens,
                          const float* __restrict__ g,
                          const float* __restrict__ b) {
    int warp = (blockIdx.x * blockDim.x + threadIdx.x) >> 5;
    int lane = threadIdx.x & 31;
    if (warp >= R_) return;
    const float* row = tokens + warp * D_;
    float v[6];
    float sum = 0.f;
#pragma unroll
    for (int i = 0; i < 6; i++) { v[i] = row[lane + i * 32]; sum += v[i]; }
#pragma unroll
    for (int o = 16; o; o >>= 1) sum += __shfl_xor_sync(0xffffffffu, sum, o);
    float mu = sum * (1.f / D_);
    float sq = 0.f;
#pragma unroll
    for (int i = 0; i < 6; i++) { float d = v[i] - mu; sq += d * d; }
#pragma unroll
    for (int o = 16; o; o >>= 1) sq += __shfl_xor_sync(0xffffffffu, sq, o);
    float inv = rsqrtf(sq * (1.f / D_) + 1e-5f);
    __nv_bfloat16* out = g_tb + warp * D_;
#pragma unroll
    for (int i = 0; i < 6; i++) {
        int c = lane + i * 32;
        out[c] = __float2bfloat16_rn((v[i] - mu) * inv * g[c] + b[c]);
    }
}

// ---------------- K2: TC GEMM t @ [Wx|Wz] -------------------------------------
__global__ void __launch_bounds__(256) gemm_xz_tc(const float* __restrict__ bx,
                                                  const float* __restrict__ bz) {
    __shared__ __align__(16) __nv_bfloat16 As[128 * AP];
    __shared__ __align__(16) __nv_bfloat16 Bs[32 * BP];
    int bm = blockIdx.y * 128;
    int bn = blockIdx.x * 64;
    int tid = threadIdx.x;
    int w = tid >> 5, lane = tid & 31;
    int wm = (w >> 1) * 32, wn = (w & 1) * 32;

    float acc[2][4][4] = {};

    for (int k0 = 0; k0 < D_; k0 += 32) {
#pragma unroll
        for (int it = 0; it < 2; it++) {
            int idx = tid + it * 256;
            int r = idx >> 2, seg = idx & 3;
            *(uint4*)&As[r * AP + seg * 8] =
                *(const uint4*)&g_tb[(bm + r) * D_ + k0 + seg * 8];
        }
        {
            int r = tid >> 3, seg = tid & 7;
            *(uint4*)&Bs[r * BP + seg * 8] =
                *(const uint4*)&g_wxz[(k0 + r) * (2 * E_) + bn + seg * 8];
        }
        __syncthreads();
#pragma unroll
        for (int kk = 0; kk < 2; kk++) {
            uint32_t a[2][4], bfr[2][4];
#pragma unroll
            for (int i = 0; i < 2; i++) {
                uint32_t ad = smem_u32(&As[(wm + i * 16 + (lane & 15)) * AP
                                           + kk * 16 + (lane >> 4) * 8]);
                ldsm_x4(a[i][0], a[i][1], a[i][2], a[i][3], ad);
            }
#pragma unroll
            for (int jp = 0; jp < 2; jp++) {
                int krow = kk * 16 + (lane & 7) + ((lane >> 3) & 1) * 8;
                uint32_t bd = smem_u32(&Bs[krow * BP + wn + jp * 16
                                           + (lane >> 4) * 8]);
                ldsm_x4_t(bfr[jp][0], bfr[jp][1], bfr[jp][2], bfr[jp][3], bd);
            }
#pragma unroll
            for (int i = 0; i < 2; i++) {
#pragma unroll
                for (int jp = 0; jp < 2; jp++) {
                    mma16816(acc[i][jp * 2 + 0], a[i], bfr[jp][0], bfr[jp][1]);
                    mma16816(acc[i][jp * 2 + 1], a[i], bfr[jp][2], bfr[jp][3]);
                }
            }
        }
        __syncthreads();
    }

    int gq = lane >> 2, tq = lane & 3;
    bool isx = (bn < E_);
#pragma unroll
    for (int i = 0; i < 2; i++) {
#pragma unroll
        for (int jj = 0; jj < 4; jj++) {
#pragma unroll
            for (int h = 0; h < 2; h++) {
                int r = bm + wm + i * 16 + gq + h * 8;
#pragma unroll
                for (int q = 0; q < 2; q++) {
                    int c = bn + wn + jj * 8 + tq * 2 + q;
                    float v = acc[i][jj][h * 2 + q];
                    if (isx) {
                        g_x[r * E_ + c] = v + bx[c];
                    } else {
                        int e = c - E_;
                        float z = v + bz[e];
                        float s = z * sigmoidf_(z);
                        g_gateb[r * E_ + e] = __float2bfloat16_rn(sigmoidf_(s));
                    }
                }
            }
        }
    }
}

// ---------------- K3a: fused depthwise conv (both dirs) -> bf16 ---------------
__global__ void conv2_kernel(const float* __restrict__ cwf, const float* __restrict__ cbf,
                             const float* __restrict__ cwb, const float* __restrict__ cbb) {
    int idx = blockIdx.x * blockDim.x + threadIdx.x;   // over RE_/4
    if (idx >= RE_ / 4) return;
    int e4 = idx % (E_ / 4);
    int r  = idx / (E_ / 4);
    int j = r & (J_ - 1);
    int e0 = e4 * 4;
    const float4 x0 = *(const float4*)&g_x[r * E_ + e0];
    float4 xm = make_float4(0.f, 0.f, 0.f, 0.f);
    float4 xp = make_float4(0.f, 0.f, 0.f, 0.f);
    if (j > 0)      xm = *(const float4*)&g_x[(r - 1) * E_ + e0];
    if (j < J_ - 1) xp = *(const float4*)&g_x[(r + 1) * E_ + e0];
    float xmv[4] = {xm.x, xm.y, xm.z, xm.w};
    float x0v[4] = {x0.x, x0.y, x0.z, x0.w};
    float xpv[4] = {xp.x, xp.y, xp.z, xp.w};
    __nv_bfloat16 f[4], bwd[4];
#pragma unroll
    for (int l = 0; l < 4; l++) {
        int e = e0 + l;
        float vf = cbf[e] + cwf[e * 3 + 0] * xmv[l] + cwf[e * 3 + 1] * x0v[l]
                          + cwf[e * 3 + 2] * xpv[l];
        float vb = cbb[e] + cwb[e * 3 + 0] * xpv[l] + cwb[e * 3 + 1] * x0v[l]
                          + cwb[e * 3 + 2] * xmv[l];
        f[l]   = __float2bfloat16_rn(vf);
        bwd[l] = __float2bfloat16_rn(vb);
    }
    *(uint2*)&g_xcf[r * E_ + e0] = *(uint2*)f;
    *(uint2*)&g_xcb[r * E_ + e0] = *(uint2*)bwd;
}

// ---------------- K3b: TC GEMM xc @ [WB|WC|WD|Wi] (per-dir) -------------------
// Writes g_bcdu transposed (coalesced via smem transpose).
__global__ void __launch_bounds__(256) gemm_proj_tc() {
    __shared__ __align__(16) char smraw[64 * 129 * 4];
    __nv_bfloat16* As = (__nv_bfloat16*)smraw;                   // 128*AP
    __nv_bfloat16* Bs = (__nv_bfloat16*)(smraw + 128 * AP * 2);  // 32*BP
    float (*sT)[129] = (float(*)[129])smraw;

    int dir = blockIdx.z;
    int bm = blockIdx.y * 128;
    int tid = threadIdx.x;
    int w = tid >> 5, lane = tid & 31;
    int wm = (w >> 1) * 32, wn = (w & 1) * 32;
    const __nv_bfloat16* Asrc = dir ? g_xcb : g_xcf;
    const __nv_bfloat16* Bsrc = g_wp + dir * (E_ * 64);

    float acc[2][4][4] = {};

    for (int k0 = 0; k0 < E_; k0 += 32) {
#pragma unroll
        for (int it = 0; it < 2; it++) {
            int idx = tid + it * 256;
            int r = idx >> 2, seg = idx & 3;
            *(uint4*)&As[r * AP + seg * 8] =
                *(const uint4*)&Asrc[(bm + r) * E_ + k0 + seg * 8];
        }
        {
            int r = tid >> 3, seg = tid & 7;
            *(uint4*)&Bs[r * BP + seg * 8] =
                *(const uint4*)&Bsrc[(k0 + r) * 64 + seg * 8];
        }
        __syncthreads();
#pragma unroll
        for (int kk = 0; kk < 2; kk++) {
            uint32_t a[2][4], bfr[2][4];
#pragma unroll
            for (int i = 0; i < 2; i++) {
                uint32_t ad = smem_u32(&As[(wm + i * 16 + (lane & 15)) * AP
                                           + kk * 16 + (lane >> 4) * 8]);
                ldsm_x4(a[i][0], a[i][1], a[i][2], a[i][3], ad);
            }
#pragma unroll
            for (int jp = 0; jp < 2; jp++) {
                int krow = kk * 16 + (lane & 7) + ((lane >> 3) & 1) * 8;
                uint32_t bd = smem_u32(&Bs[krow * BP + wn + jp * 16
                                           + (lane >> 4) * 8]);
                ldsm_x4_t(bfr[jp][0], bfr[jp][1], bfr[jp][2], bfr[jp][3], bd);
            }
#pragma unroll
            for (int i = 0; i < 2; i++) {
#pragma unroll
                for (int jp = 0; jp < 2; jp++) {
                    mma16816(acc[i][jp * 2 + 0], a[i], bfr[jp][0], bfr[jp][1]);
                    mma16816(acc[i][jp * 2 + 1], a[i], bfr[jp][2], bfr[jp][3]);
                }
            }
        }
        __syncthreads();
    }

    // transpose through smem
    int gq = lane >> 2, tq = lane & 3;
#pragma unroll
    for (int i = 0; i < 2; i++) {
#pragma unroll
        for (int jj = 0; jj < 4; jj++) {
#pragma unroll
            for (int h = 0; h < 2; h++) {
                int rr = wm + i * 16 + gq + h * 8;
#pragma unroll
                for (int q = 0; q < 2; q++) {
                    int c = wn + jj * 8 + tq * 2 + q;
                    sT[c][rr] = acc[i][jj][h * 2 + q];
                }
            }
        }
    }
    __syncthreads();

    int b = bm >> 10;
    int j0 = bm & (J_ - 1);
    for (int i = tid; i < 64 * 128; i += 256) {
        int c = i >> 7, rr = i & 127;
        float v = sT[c][rr] + g_bp[dir * 64 + c];
        int j = j0 + rr;
        int pos = dir ? (J_ - 1 - j) : j;
        g_bcdu[(b * 128 + dir * 64 + c) * J_ + pos] = v;
    }
}

// ---------------- K4: fused bidirectional selective scan ----------------------
__global__ void scan2_kernel(const float* __restrict__ A_log) {
    int b = blockIdx.x >> 4;
    int n = blockIdx.x & 15;
    int t = threadIdx.x;
    float An = -softplusf(A_log[n]);
    float inv_den = 1.f / (An + 1e-6f);
    const float* base = g_bcdu + b * 128 * J_;

    __shared__ float sAcc[J_];
    __shared__ float sP[128], sS[128];

#pragma unroll
    for (int dir = 0; dir < 2; dir++) {
        int co = dir * 64;
        const float* Bt = base + (co + n) * J_;
        const float* Ct = base + (co + 16 + n) * J_;
        const float* Dr = base + (co + 32 + n) * J_;
        const float* Ut = base + (co + 48 + n) * J_;

        int j0 = t * 8;
        float hl[8], pp[8], cc[8];
        float P = 1.f, S = 0.f;
#pragma unroll
        for (int i = 0; i < 8; i++) {
            int j = j0 + i;
            float dt = softplusf(Dr[j]);
            float ab = expf(dt * An);
            float bu = (ab - 1.f) * inv_den * Bt[j] * Ut[j];
            S = ab * S + bu;
            P = P * ab;
            hl[i] = S; pp[i] = P; cc[i] = Ct[j];
        }
        float iP = P, iS = S;
        for (int off = 1; off < 128; off <<= 1) {
            sP[t] = iP; sS[t] = iS;
            __syncthreads();
            if (t >= off) {
                float qP = sP[t - off], qS = sS[t - off];
                iS = qS * iP + iS;
                iP = qP * iP;
            }
            __syncthreads();
        }
        sS[t] = iS;
        __syncthreads();
        float Hin = (t == 0) ? 0.f : sS[t - 1];
        __syncthreads();

#pragma unroll
        for (int i = 0; i < 8; i++) {
            int j = j0 + i;
            float h = hl[i] + pp[i] * Hin;
            float sc = h * cc[i];
            if (dir == 0) sAcc[j] = sc;
            else          sAcc[J_ - 1 - j] += sc;
        }
        __syncthreads();
    }

#pragma unroll
    for (int i = 0; i < 8; i++) {
        int pos = t * 8 + i;
        g_S[(b * J_ + pos) * N_ + n] = sAcc[pos];
    }
}

// ---------------- K5: readout + gate -> bf16 ----------------------------------
__global__ void readout_kernel(const float* __restrict__ Wr,
                               const float* __restrict__ br) {
    int idx = blockIdx.x * blockDim.x + threadIdx.x;
    if (idx >= RE_) return;
    int e = idx % E_;
    int r = idx / E_;
    const float* s = g_S + r * N_;
    float acc = 0.f;
#pragma unroll
    for (int n = 0; n < N_; n++) acc += s[n] * Wr[n * E_ + e];
    float gt = __bfloat162float(g_gateb[idx]);
    g_yb[idx] = __float2bfloat16_rn((acc + 2.f * br[e]) * gt);
}

// ---------------- K6: TC GEMM y @ Wo + residual -------------------------------
__global__ void __launch_bounds__(256) gemm_out_tc(const float* __restrict__ bo,
                                                   const float* __restrict__ tokens,
                                                   float* __restrict__ out) {
    __shared__ __align__(16) __nv_bfloat16 As[128 * AP];
    __shared__ __align__(16) __nv_bfloat16 Bs[32 * BP];
    int bm = blockIdx.y * 128;
    int bn = blockIdx.x * 64;
    int tid = threadIdx.x;
    int w = tid >> 5, lane = tid & 31;
    int wm = (w >> 1) * 32, wn = (w & 1) * 32;

    float acc[2][4][4] = {};

    for (int k0 = 0; k0 < E_; k0 += 32) {
#pragma unroll
        for (int it = 0; it < 2; it++) {
            int idx = tid + it * 256;
            int r = idx >> 2, seg = idx & 3;
            *(uint4*)&As[r * AP + seg * 8] =
                *(const uint4*)&g_yb[(bm + r) * E_ + k0 + seg * 8];
        }
        {
            int r = tid >> 3, seg = tid & 7;
            *(uint4*)&Bs[r * BP + seg * 8] =
                *(const uint4*)&g_wo[(k0 + r) * D_ + bn + seg * 8];
        }
        __syncthreads();
#pragma unroll
        for (int kk = 0; kk < 2; kk++) {
            uint32_t a[2][4], bfr[2][4];
#pragma unroll
            for (int i = 0; i < 2; i++) {
                uint32_t ad = smem_u32(&As[(wm + i * 16 + (lane & 15)) * AP
                                           + kk * 16 + (lane >> 4) * 8]);
                ldsm_x4(a[i][0], a[i][1], a[i][2], a[i][3], ad);
            }
#pragma unroll
            for (int jp = 0; jp < 2; jp++) {
                int krow = kk * 16 + (lane & 7) + ((lane >> 3) & 1) * 8;
                uint32_t bd = smem_u32(&Bs[krow * BP + wn + jp * 16
                                           + (lane >> 4) * 8]);
                ldsm_x4_t(bfr[jp][0], bfr[jp][1], bfr[jp][2], bfr[jp][3], bd);
            }
#pragma unroll
            for (int i = 0; i < 2; i++) {
#pragma unroll
                for (int jp = 0; jp < 2; jp++) {
                    mma16816(acc[i][jp * 2 + 0], a[i], bfr[jp][0], bfr[jp][1]);
                    mma16816(acc[i][jp * 2 + 1], a[i], bfr[jp][2], bfr[jp][3]);
                }
            }
        }
        __syncthreads();
    }

    int gq = lane >> 2, tq = lane & 3;
#pragma unroll
    for (int i = 0; i < 2; i++) {
#pragma unroll
        for (int jj = 0; jj < 4; jj++) {
#pragma unroll
            for (int h = 0; h < 2; h++) {
                int r = bm + wm + i * 16 + gq + h * 8;
#pragma unroll
                for (int q = 0; q < 2; q++) {
                    int c = bn + wn + jj * 8 + tq * 2 + q;
                    out[r * D_ + c] = tokens[r * D_ + c]
                                    + acc[i][jj][h * 2 + q] + bo[c];
                }
            }
        }
    }
}

// ---------------- launcher ----------------------------------------------------
extern "C" void kernel_launch(void* const* d_in, const int* in_sizes, int n_in,
                              void* d_out, int out_size) {
    const float* tokens  = (const float*)d_in[0];
    const float* norm_g  = (const float*)d_in[1];
    const float* norm_b  = (const float*)d_in[2];
    const float* Wx      = (const float*)d_in[3];
    const float* bx      = (const float*)d_in[4];
    const float* Wz      = (const float*)d_in[5];
    const float* bz      = (const float*)d_in[6];
    const float* convf_w = (const float*)d_in[7];
    const float* convf_b = (const float*)d_in[8];
    const float* convb_w = (const float*)d_in[9];
    const float* convb_b = (const float*)d_in[10];
    const float* WBf = (const float*)d_in[11];
    const float* bBf = (const float*)d_in[12];
    const float* WCf = (const float*)d_in[13];
    const float* bCf = (const float*)d_in[14];
    const float* WDf = (const float*)d_in[15];
    const float* bDf = (const float*)d_in[16];
    const float* WBb = (const float*)d_in[17];
    const float* bBb = (const float*)d_in[18];
    const float* WCb = (const float*)d_in[19];
    const float* bCb = (const float*)d_in[20];
    const float* WDb = (const float*)d_in[21];
    const float* bDb = (const float*)d_in[22];
    const float* A_log = (const float*)d_in[23];
    const float* Wi  = (const float*)d_in[24];
    const float* bi  = (const float*)d_in[25];
    const float* Wr  = (const float*)d_in[26];
    const float* br  = (const float*)d_in[27];
    const float* Wo  = (const float*)d_in[28];
    const float* bo  = (const float*)d_in[29];
    float* out = (float*)d_out;

    const int nw = D_ * 2 * E_ + E_ * D_ + 2 * E_ * 64 + 128;
    wcvt_kernel<<<(nw + 255) / 256, 256>>>(Wx, Wz, Wo,
                                           WBf, WCf, WDf, WBb, WCb, WDb, Wi,
                                           bBf, bCf, bDf, bBb, bCb, bDb, bi);
    ln_kernel<<<R_ / 8, 256>>>(tokens, norm_g, norm_b);

    gemm_xz_tc<<<dim3(12, R_ / 128), 256>>>(bx, bz);

    conv2_kernel<<<(RE_ / 4 + 255) / 256, 256>>>(convf_w, convf_b, convb_w, convb_b);

    gemm_proj_tc<<<dim3(1, R_ / 128, 2), 256>>>();

    scan2_kernel<<<B_ * N_, 128>>>(A_log);

    readout_kernel<<<RE_ / 256, 256>>>(Wr, br);

    gemm_out_tc<<<dim3(3, R_ / 128), 256>>>(bo, tokens, out);
}

// round 7
// speedup vs baseline: 3.1802x; 1.0070x over previous
#include <cuda_runtime.h>
#include <cuda_bf16.h>
#include <math.h>
#include <stdint.h>

#define B_  32
#define J_  1024
#define D_  192
#define E_  384
#define N_  16
#define R_  (B_ * J_)          // 32768 rows
#define RE_ (R_ * E_)          // 12,582,912

// ---------------- scratch ----------------------------------------------------
__device__ __nv_bfloat16 g_tb[R_ * D_];      // LayerNorm output (bf16)
__device__ __nv_bfloat16 g_xb[R_ * E_];      // x = t@Wx + bx (bf16)
__device__ __nv_bfloat16 g_gateb[R_ * E_];   // sigmoid(silu(z)) bf16
__device__ __nv_bfloat16 g_xcf[R_ * E_];     // fwd conv out bf16
__device__ __nv_bfloat16 g_xcb[R_ * E_];     // bwd conv out bf16 (indexed by j)
__device__ float g_bcdu[B_ * 128 * J_];      // [b][c][j]; 0-63 fwd {B,C,D,u}, 64-127 bwd
__device__ float g_S[R_ * N_];               // S_f + flip(S_b)
__device__ __nv_bfloat16 g_yb[R_ * E_];      // gated readout (bf16)
__device__ __nv_bfloat16 g_wxz[D_ * 2 * E_]; // [192][768] packed Wx|Wz bf16
__device__ __nv_bfloat16 g_wo[E_ * D_];      // [384][192] Wo bf16
__device__ __nv_bfloat16 g_wp[2 * E_ * 64];  // per-dir packed [WB|WC|WD|Wi] bf16
__device__ float g_bp[2 * 64];               // per-dir packed biases

__device__ __forceinline__ float softplusf(float x) {
    return (x > 20.f) ? x : log1pf(expf(x));
}
__device__ __forceinline__ float sigmoidf_(float x) {
    return 1.f / (1.f + expf(-x));
}

// ---------------- primitives ---------------------------------------------------
__device__ __forceinline__ uint32_t smem_u32(const void* p) {
    return (uint32_t)__cvta_generic_to_shared(p);
}
__device__ __forceinline__ void cp_async16(void* dst, const void* src) {
    asm volatile("cp.async.cg.shared.global [%0], [%1], 16;"
                 :: "r"(smem_u32(dst)), "l"(src));
}
#define CP_COMMIT() asm volatile("cp.async.commit_group;")
#define CP_WAIT0()  asm volatile("cp.async.wait_group 0;")

__device__ __forceinline__ void ldsm_x4(uint32_t& r0, uint32_t& r1,
                                        uint32_t& r2, uint32_t& r3, uint32_t a) {
    asm volatile("ldmatrix.sync.aligned.m8n8.x4.shared.b16 {%0,%1,%2,%3}, [%4];"
                 : "=r"(r0), "=r"(r1), "=r"(r2), "=r"(r3) : "r"(a));
}
__device__ __forceinline__ void ldsm_x4_t(uint32_t& r0, uint32_t& r1,
                                          uint32_t& r2, uint32_t& r3, uint32_t a) {
    asm volatile("ldmatrix.sync.aligned.m8n8.x4.trans.shared.b16 {%0,%1,%2,%3}, [%4];"
                 : "=r"(r0), "=r"(r1), "=r"(r2), "=r"(r3) : "r"(a));
}
__device__ __forceinline__ void mma16816(float* d, const uint32_t* a,
                                         uint32_t b0, uint32_t b1) {
    asm volatile(
        "mma.sync.aligned.m16n8k16.row.col.f32.bf16.bf16.f32 "
        "{%0,%1,%2,%3}, {%4,%5,%6,%7}, {%8,%9}, {%0,%1,%2,%3};"
        : "+f"(d[0]), "+f"(d[1]), "+f"(d[2]), "+f"(d[3])
        : "r"(a[0]), "r"(a[1]), "r"(a[2]), "r"(a[3]), "r"(b0), "r"(b1));
}

#define AP 40   // A smem row stride (bf16)
#define BP 72   // B smem row stride (bf16)

// shared compute body: one BK=32 chunk of mma on the given stage buffers
__device__ __forceinline__ void mma_chunk(const __nv_bfloat16* As,
                                          const __nv_bfloat16* Bs,
                                          int wm, int wn, int lane,
                                          float acc[2][4][4]) {
#pragma unroll
    for (int kk = 0; kk < 2; kk++) {
        uint32_t a[2][4], bfr[2][4];
#pragma unroll
        for (int i = 0; i < 2; i++) {
            uint32_t ad = smem_u32(&As[(wm + i * 16 + (lane & 15)) * AP
                                       + kk * 16 + (lane >> 4) * 8]);
            ldsm_x4(a[i][0], a[i][1], a[i][2], a[i][3], ad);
        }
#pragma unroll
        for (int jp = 0; jp < 2; jp++) {
            int krow = kk * 16 + (lane & 7) + ((lane >> 3) & 1) * 8;
            uint32_t bd = smem_u32(&Bs[krow * BP + wn + jp * 16
                                       + (lane >> 4) * 8]);
            ldsm_x4_t(bfr[jp][0], bfr[jp][1], bfr[jp][2], bfr[jp][3], bd);
        }
#pragma unroll
        for (int i = 0; i < 2; i++) {
#pragma unroll
            for (int jp = 0; jp < 2; jp++) {
                mma16816(acc[i][jp * 2 + 0], a[i], bfr[jp][0], bfr[jp][1]);
                mma16816(acc[i][jp * 2 + 1], a[i], bfr[jp][2], bfr[jp][3]);
            }
        }
    }
}

// ---------------- K0: weight conversion / packing -----------------------------
__global__ void wcvt_kernel(const float* __restrict__ Wx, const float* __restrict__ Wz,
                            const float* __restrict__ Wo,
                            const float* __restrict__ WBf, const float* __restrict__ WCf,
                            const float* __restrict__ WDf,
                            const float* __restrict__ WBb, const float* __restrict__ WCb,
                            const float* __restrict__ WDb,
                            const float* __restrict__ Wi,
                            const float* __restrict__ bBf, const float* __restrict__ bCf,
                            const float* __restrict__ bDf,
                            const float* __restrict__ bBb, const float* __restrict__ bCb,
                            const float* __restrict__ bDb,
                            const float* __restrict__ bi) {
    const int nxz = D_ * 2 * E_;
    const int nwo = E_ * D_;
    const int nwp = 2 * E_ * 64;
    int i = blockIdx.x * blockDim.x + threadIdx.x;
    if (i < nxz) {
        int k = i / (2 * E_), c = i % (2 * E_);
        float v = (c < E_) ? Wx[k * E_ + c] : Wz[k * E_ + c - E_];
        g_wxz[i] = __float2bfloat16_rn(v);
    } else if (i < nxz + nwo) {
        int j = i - nxz;
        g_wo[j] = __float2bfloat16_rn(Wo[j]);
    } else if (i < nxz + nwo + nwp) {
        int j = i - nxz - nwo;
        int dir = j / (E_ * 64);
        int rem = j % (E_ * 64);
        int k = rem / 64, c = rem % 64;
        const float* W;
        int p = c >> 4;
        if (p == 3) W = Wi;
        else if (dir == 0) W = (p == 0) ? WBf : (p == 1) ? WCf : WDf;
        else               W = (p == 0) ? WBb : (p == 1) ? WCb : WDb;
        g_wp[j] = __float2bfloat16_rn(W[k * N_ + (c & 15)]);
    } else if (i < nxz + nwo + nwp + 128) {
        int j = i - nxz - nwo - nwp;
        int dir = j >> 6, c = j & 63;
        int p = c >> 4;
        const float* bb;
        if (p == 3) bb = bi;
        else if (dir == 0) bb = (p == 0) ? bBf : (p == 1) ? bCf : bDf;
        else               bb = (p == 0) ? bBb : (p == 1) ? bCb : bDb;
        g_bp[j] = bb[c & 15];
    }
}

// ---------------- K1: LayerNorm -> bf16 ---------------------------------------
__global__ void ln_kernel(const float* __restrict__ tokens,
                          const float* __restrict__ g,
                          const float* __restrict__ b) {
    int warp = (blockIdx.x * blockDim.x + threadIdx.x) >> 5;
    int lane = threadIdx.x & 31;
    if (warp >= R_) return;
    const float* row = tokens + warp * D_;
    float v[6];
    float sum = 0.f;
#pragma unroll
    for (int i = 0; i < 6; i++) { v[i] = row[lane + i * 32]; sum += v[i]; }
#pragma unroll
    for (int o = 16; o; o >>= 1) sum += __shfl_xor_sync(0xffffffffu, sum, o);
    float mu = sum * (1.f / D_);
    float sq = 0.f;
#pragma unroll
    for (int i = 0; i < 6; i++) { float d = v[i] - mu; sq += d * d; }
#pragma unroll
    for (int o = 16; o; o >>= 1) sq += __shfl_xor_sync(0xffffffffu, sq, o);
    float inv = rsqrtf(sq * (1.f / D_) + 1e-5f);
    __nv_bfloat16* out = g_tb + warp * D_;
#pragma unroll
    for (int i = 0; i < 6; i++) {
        int c = lane + i * 32;
        out[c] = __float2bfloat16_rn((v[i] - mu) * inv * g[c] + b[c]);
    }
}

// ---------------- K2: TC GEMM t @ [Wx|Wz], double-buffered --------------------
__global__ void __launch_bounds__(256) gemm_xz_tc(const float* __restrict__ bx,
                                                  const float* __restrict__ bz) {
    __shared__ __align__(16) __nv_bfloat16 As[2][128 * AP];
    __shared__ __align__(16) __nv_bfloat16 Bs[2][32 * BP];
    int bm = blockIdx.y * 128;
    int bn = blockIdx.x * 64;
    int tid = threadIdx.x;
    int w = tid >> 5, lane = tid & 31;
    int wm = (w >> 1) * 32, wn = (w & 1) * 32;

    float acc[2][4][4] = {};
    const int NK = D_ / 32;   // 6

    auto load_stage = [&](int s, int k0) {
#pragma unroll
        for (int it = 0; it < 2; it++) {
            int idx = tid + it * 256;
            int r = idx >> 2, seg = idx & 3;
            cp_async16(&As[s][r * AP + seg * 8],
                       &g_tb[(bm + r) * D_ + k0 + seg * 8]);
        }
        {
            int r = tid >> 3, seg = tid & 7;
            cp_async16(&Bs[s][r * BP + seg * 8],
                       &g_wxz[(k0 + r) * (2 * E_) + bn + seg * 8]);
        }
        CP_COMMIT();
    };

    load_stage(0, 0);
    for (int i = 0; i < NK; i++) {
        CP_WAIT0();
        __syncthreads();
        if (i + 1 < NK) load_stage((i + 1) & 1, (i + 1) * 32);
        mma_chunk(As[i & 1], Bs[i & 1], wm, wn, lane, acc);
        __syncthreads();
    }

    int gq = lane >> 2, tq = lane & 3;
    bool isx = (bn < E_);
#pragma unroll
    for (int i = 0; i < 2; i++) {
#pragma unroll
        for (int jj = 0; jj < 4; jj++) {
#pragma unroll
            for (int h = 0; h < 2; h++) {
                int r = bm + wm + i * 16 + gq + h * 8;
#pragma unroll
                for (int q = 0; q < 2; q++) {
                    int c = bn + wn + jj * 8 + tq * 2 + q;
                    float v = acc[i][jj][h * 2 + q];
                    if (isx) {
                        g_xb[r * E_ + c] = __float2bfloat16_rn(v + bx[c]);
                    } else {
                        int e = c - E_;
                        float z = v + bz[e];
                        float s = z * sigmoidf_(z);
                        g_gateb[r * E_ + e] = __float2bfloat16_rn(sigmoidf_(s));
                    }
                }
            }
        }
    }
}

// ---------------- K3a: smem-tiled dual-direction depthwise conv ---------------
__global__ void __launch_bounds__(256) conv2s_kernel(
        const float* __restrict__ cwf, const float* __restrict__ cbf,
        const float* __restrict__ cwb, const float* __restrict__ cbb) {
    __shared__ __nv_bfloat16 xs[34][E_];     // 26112 B
    __shared__ float wf[3 * E_], wb[3 * E_], bfs[E_], bbs[E_];
    int b = blockIdx.x >> 5;
    int j0 = (blockIdx.x & 31) * 32;
    int tid = threadIdx.x;

    for (int i = tid; i < 3 * E_; i += 256) { wf[i] = cwf[i]; wb[i] = cwb[i]; }
    for (int i = tid; i < E_; i += 256)     { bfs[i] = cbf[i]; bbs[i] = cbb[i]; }
    for (int i = tid; i < 34 * (E_ / 8); i += 256) {
        int rr = i / (E_ / 8), seg = i % (E_ / 8);
        int j = j0 - 1 + rr;
        uint4 v = make_uint4(0u, 0u, 0u, 0u);
        if (j >= 0 && j < J_)
            v = *(const uint4*)&g_xb[(b * J_ + j) * E_ + seg * 8];
        *(uint4*)&xs[rr][seg * 8] = v;
    }
    __syncthreads();

    for (int i = tid; i < 32 * (E_ / 4); i += 256) {
        int r = i / (E_ / 4);
        int e0 = (i % (E_ / 4)) * 4;
        __nv_bfloat16 f[4], bwd[4];
#pragma unroll
        for (int l = 0; l < 4; l++) {
            int e = e0 + l;
            float xm = __bfloat162float(xs[r][e]);
            float x0 = __bfloat162float(xs[r + 1][e]);
            float xp = __bfloat162float(xs[r + 2][e]);
            float vf = bfs[e] + wf[e * 3 + 0] * xm + wf[e * 3 + 1] * x0
                              + wf[e * 3 + 2] * xp;
            float vb = bbs[e] + wb[e * 3 + 0] * xp + wb[e * 3 + 1] * x0
                              + wb[e * 3 + 2] * xm;
            f[l]   = __float2bfloat16_rn(vf);
            bwd[l] = __float2bfloat16_rn(vb);
        }
        int off = (b * J_ + j0 + r) * E_ + e0;
        *(uint2*)&g_xcf[off] = *(uint2*)f;
        *(uint2*)&g_xcb[off] = *(uint2*)bwd;
    }
}

// ---------------- K3b: TC GEMM xc @ [WB|WC|WD|Wi], double-buffered ------------
// smem union: mma stages (29696 B) vs fp32 transpose 64x129 (33024 B) -> 33024 B
__global__ void __launch_bounds__(256) gemm_proj_tc() {
    __shared__ __align__(16) char smraw[33024];
    __nv_bfloat16* Asb = (__nv_bfloat16*)smraw;                      // [2][128*AP] = 20480 B
    __nv_bfloat16* Bsb = (__nv_bfloat16*)(smraw + 2 * 128 * AP * 2); // [2][32*BP]  =  9216 B
    float (*sT)[129] = (float(*)[129])smraw;                          // 64*129*4    = 33024 B

    int dir = blockIdx.z;
    int bm = blockIdx.y * 128;
    int tid = threadIdx.x;
    int w = tid >> 5, lane = tid & 31;
    int wm = (w >> 1) * 32, wn = (w & 1) * 32;
    const __nv_bfloat16* Asrc = dir ? g_xcb : g_xcf;
    const __nv_bfloat16* Bsrc = g_wp + dir * (E_ * 64);

    float acc[2][4][4] = {};
    const int NK = E_ / 32;   // 12

    auto load_stage = [&](int s, int k0) {
#pragma unroll
        for (int it = 0; it < 2; it++) {
            int idx = tid + it * 256;
            int r = idx >> 2, seg = idx & 3;
            cp_async16(&Asb[s * 128 * AP + r * AP + seg * 8],
                       &Asrc[(bm + r) * E_ + k0 + seg * 8]);
        }
        {
            int r = tid >> 3, seg = tid & 7;
            cp_async16(&Bsb[s * 32 * BP + r * BP + seg * 8],
                       &Bsrc[(k0 + r) * 64 + seg * 8]);
        }
        CP_COMMIT();
    };

    load_stage(0, 0);
    for (int i = 0; i < NK; i++) {
        CP_WAIT0();
        __syncthreads();
        if (i + 1 < NK) load_stage((i + 1) & 1, (i + 1) * 32);
        mma_chunk(&Asb[(i & 1) * 128 * AP], &Bsb[(i & 1) * 32 * BP],
                  wm, wn, lane, acc);
        __syncthreads();
    }

    // transpose through smem (mma reads all done)
    int gq = lane >> 2, tq = lane & 3;
#pragma unroll
    for (int i = 0; i < 2; i++) {
#pragma unroll
        for (int jj = 0; jj < 4; jj++) {
#pragma unroll
            for (int h = 0; h < 2; h++) {
                int rr = wm + i * 16 + gq + h * 8;
#pragma unroll
                for (int q = 0; q < 2; q++) {
                    int c = wn + jj * 8 + tq * 2 + q;
                    sT[c][rr] = acc[i][jj][h * 2 + q];
                }
            }
        }
    }
    __syncthreads();

    int b = bm >> 10;
    int j0 = bm & (J_ - 1);
    for (int i = tid; i < 64 * 128; i += 256) {
        int c = i >> 7, rr = i & 127;
        float v = sT[c][rr] + g_bp[dir * 64 + c];
        int j = j0 + rr;
        int pos = dir ? (J_ - 1 - j) : j;
        g_bcdu[(b * 128 + dir * 64 + c) * J_ + pos] = v;
    }
}

// ---------------- K4: fused bidirectional selective scan ----------------------
__global__ void scan2_kernel(const float* __restrict__ A_log) {
    int b = blockIdx.x >> 4;
    int n = blockIdx.x & 15;
    int t = threadIdx.x;
    float An = -softplusf(A_log[n]);
    float inv_den = 1.f / (An + 1e-6f);
    const float* base = g_bcdu + b * 128 * J_;

    __shared__ float sAcc[J_];
    __shared__ float sP[128], sS[128];

#pragma unroll
    for (int dir = 0; dir < 2; dir++) {
        int co = dir * 64;
        const float* Bt = base + (co + n) * J_;
        const float* Ct = base + (co + 16 + n) * J_;
        const float* Dr = base + (co + 32 + n) * J_;
        const float* Ut = base + (co + 48 + n) * J_;

        int j0 = t * 8;
        float hl[8], pp[8], cc[8];
        float P = 1.f, S = 0.f;
#pragma unroll
        for (int i = 0; i < 8; i++) {
            int j = j0 + i;
            float dt = softplusf(Dr[j]);
            float ab = expf(dt * An);
            float bu = (ab - 1.f) * inv_den * Bt[j] * Ut[j];
            S = ab * S + bu;
            P = P * ab;
            hl[i] = S; pp[i] = P; cc[i] = Ct[j];
        }
        float iP = P, iS = S;
        for (int off = 1; off < 128; off <<= 1) {
            sP[t] = iP; sS[t] = iS;
            __syncthreads();
            if (t >= off) {
                float qP = sP[t - off], qS = sS[t - off];
                iS = qS * iP + iS;
                iP = qP * iP;
            }
            __syncthreads();
        }
        sS[t] = iS;
        __syncthreads();
        float Hin = (t == 0) ? 0.f : sS[t - 1];
        __syncthreads();

#pragma unroll
        for (int i = 0; i < 8; i++) {
            int j = j0 + i;
            float h = hl[i] + pp[i] * Hin;
            float sc = h * cc[i];
            if (dir == 0) sAcc[j] = sc;
            else          sAcc[J_ - 1 - j] += sc;
        }
        __syncthreads();
    }

#pragma unroll
    for (int i = 0; i < 8; i++) {
        int pos = t * 8 + i;
        g_S[(b * J_ + pos) * N_ + n] = sAcc[pos];
    }
}

// ---------------- K5: readout + gate -> bf16 ----------------------------------
__global__ void readout_kernel(const float* __restrict__ Wr,
                               const float* __restrict__ br) {
    int idx = blockIdx.x * blockDim.x + threadIdx.x;
    if (idx >= RE_) return;
    int e = idx % E_;
    int r = idx / E_;
    const float* s = g_S + r * N_;
    float acc = 0.f;
#pragma unroll
    for (int n = 0; n < N_; n++) acc += s[n] * Wr[n * E_ + e];
    float gt = __bfloat162float(g_gateb[idx]);
    g_yb[idx] = __float2bfloat16_rn((acc + 2.f * br[e]) * gt);
}

// ---------------- K6: TC GEMM y @ Wo + residual, double-buffered --------------
__global__ void __launch_bounds__(256) gemm_out_tc(const float* __restrict__ bo,
                                                   const float* __restrict__ tokens,
                                                   float* __restrict__ out) {
    __shared__ __align__(16) __nv_bfloat16 As[2][128 * AP];
    __shared__ __align__(16) __nv_bfloat16 Bs[2][32 * BP];
    int bm = blockIdx.y * 128;
    int bn = blockIdx.x * 64;
    int tid = threadIdx.x;
    int w = tid >> 5, lane = tid & 31;
    int wm = (w >> 1) * 32, wn = (w & 1) * 32;

    float acc[2][4][4] = {};
    const int NK = E_ / 32;   // 12

    auto load_stage = [&](int s, int k0) {
#pragma unroll
        for (int it = 0; it < 2; it++) {
            int idx = tid + it * 256;
            int r = idx >> 2, seg = idx & 3;
            cp_async16(&As[s][r * AP + seg * 8],
                       &g_yb[(bm + r) * E_ + k0 + seg * 8]);
        }
        {
            int r = tid >> 3, seg = tid & 7;
            cp_async16(&Bs[s][r * BP + seg * 8],
                       &g_wo[(k0 + r) * D_ + bn + seg * 8]);
        }
        CP_COMMIT();
    };

    load_stage(0, 0);
    for (int i = 0; i < NK; i++) {
        CP_WAIT0();
        __syncthreads();
        if (i + 1 < NK) load_stage((i + 1) & 1, (i + 1) * 32);
        mma_chunk(As[i & 1], Bs[i & 1], wm, wn, lane, acc);
        __syncthreads();
    }

    int gq = lane >> 2, tq = lane & 3;
#pragma unroll
    for (int i = 0; i < 2; i++) {
#pragma unroll
        for (int jj = 0; jj < 4; jj++) {
#pragma unroll
            for (int h = 0; h < 2; h++) {
                int r = bm + wm + i * 16 + gq + h * 8;
#pragma unroll
                for (int q = 0; q < 2; q++) {
                    int c = bn + wn + jj * 8 + tq * 2 + q;
                    out[r * D_ + c] = tokens[r * D_ + c]
                                    + acc[i][jj][h * 2 + q] + bo[c];
                }
            }
        }
    }
}

// ---------------- launcher ----------------------------------------------------
extern "C" void kernel_launch(void* const* d_in, const int* in_sizes, int n_in,
                              void* d_out, int out_size) {
    const float* tokens  = (const float*)d_in[0];
    const float* norm_g  = (const float*)d_in[1];
    const float* norm_b  = (const float*)d_in[2];
    const float* Wx      = (const float*)d_in[3];
    const float* bx      = (const float*)d_in[4];
    const float* Wz      = (const float*)d_in[5];
    const float* bz      = (const float*)d_in[6];
    const float* convf_w = (const float*)d_in[7];
    const float* convf_b = (const float*)d_in[8];
    const float* convb_w = (const float*)d_in[9];
    const float* convb_b = (const float*)d_in[10];
    const float* WBf = (const float*)d_in[11];
    const float* bBf = (const float*)d_in[12];
    const float* WCf = (const float*)d_in[13];
    const float* bCf = (const float*)d_in[14];
    const float* WDf = (const float*)d_in[15];
    const float* bDf = (const float*)d_in[16];
    const float* WBb = (const float*)d_in[17];
    const float* bBb = (const float*)d_in[18];
    const float* WCb = (const float*)d_in[19];
    const float* bCb = (const float*)d_in[20];
    const float* WDb = (const float*)d_in[21];
    const float* bDb = (const float*)d_in[22];
    const float* A_log = (const float*)d_in[23];
    const float* Wi  = (const float*)d_in[24];
    const float* bi  = (const float*)d_in[25];
    const float* Wr  = (const float*)d_in[26];
    const float* br  = (const float*)d_in[27];
    const float* Wo  = (const float*)d_in[28];
    const float* bo  = (const float*)d_in[29];
    float* out = (float*)d_out;

    const int nw = D_ * 2 * E_ + E_ * D_ + 2 * E_ * 64 + 128;
    wcvt_kernel<<<(nw + 255) / 256, 256>>>(Wx, Wz, Wo,
                                           WBf, WCf, WDf, WBb, WCb, WDb, Wi,
                                           bBf, bCf, bDf, bBb, bCb, bDb, bi);
    ln_kernel<<<R_ / 8, 256>>>(tokens, norm_g, norm_b);

    gemm_xz_tc<<<dim3(12, R_ / 128), 256>>>(bx, bz);

    conv2s_kernel<<<B_ * 32, 256>>>(convf_w, convf_b, convb_w, convb_b);

    gemm_proj_tc<<<dim3(1, R_ / 128, 2), 256>>>();

    scan2_kernel<<<B_ * N_, 128>>>(A_log);

    readout_kernel<<<RE_ / 256, 256>>>(Wr, br);

    gemm_out_tc<<<dim3(3, R_ / 128), 256>>>(bo, tokens, out);
}

// round 8
// speedup vs baseline: 3.2048x; 1.0077x over previous
#include <cuda_runtime.h>
#include <cuda_bf16.h>
#include <math.h>
#include <stdint.h>

#define B_  32
#define J_  1024
#define D_  192
#define E_  384
#define N_  16
#define R_  (B_ * J_)          // 32768 rows
#define RE_ (R_ * E_)          // 12,582,912

// ---------------- scratch ----------------------------------------------------
__device__ __nv_bfloat16 g_tb[R_ * D_];      // LayerNorm output (bf16)
__device__ __nv_bfloat16 g_xb[R_ * E_];      // x = t@Wx + bx (bf16)
__device__ __nv_bfloat16 g_gateb[R_ * E_];   // sigmoid(silu(z)) bf16
__device__ __nv_bfloat16 g_xcf[R_ * E_];     // fwd conv out bf16
__device__ __nv_bfloat16 g_xcb[R_ * E_];     // bwd conv out bf16 (indexed by j)
__device__ float g_bcdu[B_ * 128 * J_];      // [b][c][j]; 0-63 fwd {B,C,D,u}, 64-127 bwd
__device__ float g_S[R_ * N_];               // S_f + flip(S_b)
__device__ __nv_bfloat16 g_yb[R_ * E_];      // gated readout (bf16)
__device__ __nv_bfloat16 g_wxz[D_ * 2 * E_]; // [192][768] packed Wx|Wz bf16
__device__ __nv_bfloat16 g_wo[E_ * D_];      // [384][192] Wo bf16
__device__ __nv_bfloat16 g_wp[2 * E_ * 64];  // per-dir packed [WB|WC|WD|Wi] bf16
__device__ float g_bp[2 * 64];               // per-dir packed biases
__device__ __nv_bfloat16 g_wrt[E_ * 16];     // Wr transposed [e][n] bf16

__device__ __forceinline__ float softplusf(float x) {
    return (x > 20.f) ? x : log1pf(expf(x));
}
__device__ __forceinline__ float sigmoidf_(float x) {
    return 1.f / (1.f + expf(-x));
}

// ---------------- primitives ---------------------------------------------------
__device__ __forceinline__ uint32_t smem_u32(const void* p) {
    return (uint32_t)__cvta_generic_to_shared(p);
}
__device__ __forceinline__ void cp_async16(void* dst, const void* src) {
    asm volatile("cp.async.cg.shared.global [%0], [%1], 16;"
                 :: "r"(smem_u32(dst)), "l"(src));
}
#define CP_COMMIT() asm volatile("cp.async.commit_group;")
#define CP_WAIT0()  asm volatile("cp.async.wait_group 0;")

__device__ __forceinline__ void ldsm_x4(uint32_t& r0, uint32_t& r1,
                                        uint32_t& r2, uint32_t& r3, uint32_t a) {
    asm volatile("ldmatrix.sync.aligned.m8n8.x4.shared.b16 {%0,%1,%2,%3}, [%4];"
                 : "=r"(r0), "=r"(r1), "=r"(r2), "=r"(r3) : "r"(a));
}
__device__ __forceinline__ void ldsm_x4_t(uint32_t& r0, uint32_t& r1,
                                          uint32_t& r2, uint32_t& r3, uint32_t a) {
    asm volatile("ldmatrix.sync.aligned.m8n8.x4.trans.shared.b16 {%0,%1,%2,%3}, [%4];"
                 : "=r"(r0), "=r"(r1), "=r"(r2), "=r"(r3) : "r"(a));
}
__device__ __forceinline__ void mma16816(float* d, const uint32_t* a,
                                         uint32_t b0, uint32_t b1) {
    asm volatile(
        "mma.sync.aligned.m16n8k16.row.col.f32.bf16.bf16.f32 "
        "{%0,%1,%2,%3}, {%4,%5,%6,%7}, {%8,%9}, {%0,%1,%2,%3};"
        : "+f"(d[0]), "+f"(d[1]), "+f"(d[2]), "+f"(d[3])
        : "r"(a[0]), "r"(a[1]), "r"(a[2]), "r"(a[3]), "r"(b0), "r"(b1));
}

#define AP 40   // A smem row stride (bf16)
#define BP 72   // B smem row stride (bf16)

__device__ __forceinline__ void mma_chunk(const __nv_bfloat16* As,
                                          const __nv_bfloat16* Bs,
                                          int wm, int wn, int lane,
                                          float acc[2][4][4]) {
#pragma unroll
    for (int kk = 0; kk < 2; kk++) {
        uint32_t a[2][4], bfr[2][4];
#pragma unroll
        for (int i = 0; i < 2; i++) {
            uint32_t ad = smem_u32(&As[(wm + i * 16 + (lane & 15)) * AP
                                       + kk * 16 + (lane >> 4) * 8]);
            ldsm_x4(a[i][0], a[i][1], a[i][2], a[i][3], ad);
        }
#pragma unroll
        for (int jp = 0; jp < 2; jp++) {
            int krow = kk * 16 + (lane & 7) + ((lane >> 3) & 1) * 8;
            uint32_t bd = smem_u32(&Bs[krow * BP + wn + jp * 16
                                       + (lane >> 4) * 8]);
            ldsm_x4_t(bfr[jp][0], bfr[jp][1], bfr[jp][2], bfr[jp][3], bd);
        }
#pragma unroll
        for (int i = 0; i < 2; i++) {
#pragma unroll
            for (int jp = 0; jp < 2; jp++) {
                mma16816(acc[i][jp * 2 + 0], a[i], bfr[jp][0], bfr[jp][1]);
                mma16816(acc[i][jp * 2 + 1], a[i], bfr[jp][2], bfr[jp][3]);
            }
        }
    }
}

// ---------------- K0: weight conversion / packing -----------------------------
__global__ void wcvt_kernel(const float* __restrict__ Wx, const float* __restrict__ Wz,
                            const float* __restrict__ Wo,
                            const float* __restrict__ WBf, const float* __restrict__ WCf,
                            const float* __restrict__ WDf,
                            const float* __restrict__ WBb, const float* __restrict__ WCb,
                            const float* __restrict__ WDb,
                            const float* __restrict__ Wi,
                            const float* __restrict__ bBf, const float* __restrict__ bCf,
                            const float* __restrict__ bDf,
                            const float* __restrict__ bBb, const float* __restrict__ bCb,
                            const float* __restrict__ bDb,
                            const float* __restrict__ bi,
                            const float* __restrict__ Wr) {
    const int nxz = D_ * 2 * E_;
    const int nwo = E_ * D_;
    const int nwp = 2 * E_ * 64;
    const int nwr = E_ * 16;
    int i = blockIdx.x * blockDim.x + threadIdx.x;
    if (i < nxz) {
        int k = i / (2 * E_), c = i % (2 * E_);
        float v = (c < E_) ? Wx[k * E_ + c] : Wz[k * E_ + c - E_];
        g_wxz[i] = __float2bfloat16_rn(v);
    } else if (i < nxz + nwo) {
        int j = i - nxz;
        g_wo[j] = __float2bfloat16_rn(Wo[j]);
    } else if (i < nxz + nwo + nwp) {
        int j = i - nxz - nwo;
        int dir = j / (E_ * 64);
        int rem = j % (E_ * 64);
        int k = rem / 64, c = rem % 64;
        const float* W;
        int p = c >> 4;
        if (p == 3) W = Wi;
        else if (dir == 0) W = (p == 0) ? WBf : (p == 1) ? WCf : WDf;
        else               W = (p == 0) ? WBb : (p == 1) ? WCb : WDb;
        g_wp[j] = __float2bfloat16_rn(W[k * N_ + (c & 15)]);
    } else if (i < nxz + nwo + nwp + nwr) {
        int j = i - nxz - nwo - nwp;
        int e = j >> 4, n = j & 15;
        g_wrt[j] = __float2bfloat16_rn(Wr[n * E_ + e]);
    } else if (i < nxz + nwo + nwp + nwr + 128) {
        int j = i - nxz - nwo - nwp - nwr;
        int dir = j >> 6, c = j & 63;
        int p = c >> 4;
        const float* bb;
        if (p == 3) bb = bi;
        else if (dir == 0) bb = (p == 0) ? bBf : (p == 1) ? bCf : bDf;
        else               bb = (p == 0) ? bBb : (p == 1) ? bCb : bDb;
        g_bp[j] = bb[c & 15];
    }
}

// ---------------- K1: LayerNorm -> bf16 ---------------------------------------
__global__ void ln_kernel(const float* __restrict__ tokens,
                          const float* __restrict__ g,
                          const float* __restrict__ b) {
    int warp = (blockIdx.x * blockDim.x + threadIdx.x) >> 5;
    int lane = threadIdx.x & 31;
    if (warp >= R_) return;
    const float* row = tokens + warp * D_;
    float v[6];
    float sum = 0.f;
#pragma unroll
    for (int i = 0; i < 6; i++) { v[i] = row[lane + i * 32]; sum += v[i]; }
#pragma unroll
    for (int o = 16; o; o >>= 1) sum += __shfl_xor_sync(0xffffffffu, sum, o);
    float mu = sum * (1.f / D_);
    float sq = 0.f;
#pragma unroll
    for (int i = 0; i < 6; i++) { float d = v[i] - mu; sq += d * d; }
#pragma unroll
    for (int o = 16; o; o >>= 1) sq += __shfl_xor_sync(0xffffffffu, sq, o);
    float inv = rsqrtf(sq * (1.f / D_) + 1e-5f);
    __nv_bfloat16* out = g_tb + warp * D_;
#pragma unroll
    for (int i = 0; i < 6; i++) {
        int c = lane + i * 32;
        out[c] = __float2bfloat16_rn((v[i] - mu) * inv * g[c] + b[c]);
    }
}

// ---------------- K2: TC GEMM t @ [Wx|Wz], double-buffered --------------------
__global__ void __launch_bounds__(256) gemm_xz_tc(const float* __restrict__ bx,
                                                  const float* __restrict__ bz) {
    __shared__ __align__(16) __nv_bfloat16 As[2][128 * AP];
    __shared__ __align__(16) __nv_bfloat16 Bs[2][32 * BP];
    int bm = blockIdx.y * 128;
    int bn = blockIdx.x * 64;
    int tid = threadIdx.x;
    int w = tid >> 5, lane = tid & 31;
    int wm = (w >> 1) * 32, wn = (w & 1) * 32;

    float acc[2][4][4] = {};
    const int NK = D_ / 32;   // 6

    auto load_stage = [&](int s, int k0) {
#pragma unroll
        for (int it = 0; it < 2; it++) {
            int idx = tid + it * 256;
            int r = idx >> 2, seg = idx & 3;
            cp_async16(&As[s][r * AP + seg * 8],
                       &g_tb[(bm + r) * D_ + k0 + seg * 8]);
        }
        {
            int r = tid >> 3, seg = tid & 7;
            cp_async16(&Bs[s][r * BP + seg * 8],
                       &g_wxz[(k0 + r) * (2 * E_) + bn + seg * 8]);
        }
        CP_COMMIT();
    };

    load_stage(0, 0);
    for (int i = 0; i < NK; i++) {
        CP_WAIT0();
        __syncthreads();
        if (i + 1 < NK) load_stage((i + 1) & 1, (i + 1) * 32);
        mma_chunk(As[i & 1], Bs[i & 1], wm, wn, lane, acc);
        __syncthreads();
    }

    int gq = lane >> 2, tq = lane & 3;
    bool isx = (bn < E_);
#pragma unroll
    for (int i = 0; i < 2; i++) {
#pragma unroll
        for (int jj = 0; jj < 4; jj++) {
#pragma unroll
            for (int h = 0; h < 2; h++) {
                int r = bm + wm + i * 16 + gq + h * 8;
#pragma unroll
                for (int q = 0; q < 2; q++) {
                    int c = bn + wn + jj * 8 + tq * 2 + q;
                    float v = acc[i][jj][h * 2 + q];
                    if (isx) {
                        g_xb[r * E_ + c] = __float2bfloat16_rn(v + bx[c]);
                    } else {
                        int e = c - E_;
                        float z = v + bz[e];
                        float s = z * sigmoidf_(z);
                        g_gateb[r * E_ + e] = __float2bfloat16_rn(sigmoidf_(s));
                    }
                }
            }
        }
    }
}

// ---------------- K3a: register-sliding dual-direction depthwise conv ---------
// Thread = (batch, 16-step j-strip, 4-channel quad). Weights in registers,
// x rows slide through registers; 1 uint2 load + 2 uint2 stores per step.
__global__ void __launch_bounds__(256) conv3_kernel(
        const float* __restrict__ cwf, const float* __restrict__ cbf,
        const float* __restrict__ cwb, const float* __restrict__ cbb) {
    const int NQ = E_ / 4;            // 96
    int idx = blockIdx.x * blockDim.x + threadIdx.x;
    if (idx >= B_ * (J_ / 16) * NQ) return;
    int q = idx % NQ;
    int rest = idx / NQ;
    int strip = rest % (J_ / 16);
    int b = rest / (J_ / 16);
    int e0 = q * 4;
    int j0 = strip * 16;

    float w0f[4], w1f[4], w2f[4], bf[4];
    float w0b[4], w1b[4], w2b[4], bb[4];
#pragma unroll
    for (int l = 0; l < 4; l++) {
        int e = e0 + l;
        w0f[l] = cwf[e * 3 + 0]; w1f[l] = cwf[e * 3 + 1]; w2f[l] = cwf[e * 3 + 2];
        w0b[l] = cwb[e * 3 + 0]; w1b[l] = cwb[e * 3 + 1]; w2b[l] = cwb[e * 3 + 2];
        bf[l] = cbf[e];          bb[l] = cbb[e];
    }

    const __nv_bfloat16* xrow = g_xb + (b * J_) * E_ + e0;
    float xm[4], x0[4], xp[4];

    auto load_row = [&](int j, float* dst) {
        if (j >= 0 && j < J_) {
            uint2 raw = *(const uint2*)&xrow[j * E_];
            const __nv_bfloat16* h = (const __nv_bfloat16*)&raw;
#pragma unroll
            for (int l = 0; l < 4; l++) dst[l] = __bfloat162float(h[l]);
        } else {
#pragma unroll
            for (int l = 0; l < 4; l++) dst[l] = 0.f;
        }
    };

    load_row(j0 - 1, xm);
    load_row(j0, x0);

#pragma unroll
    for (int jj = 0; jj < 16; jj++) {
        int j = j0 + jj;
        load_row(j + 1, xp);
        __nv_bfloat16 f[4], bw[4];
#pragma unroll
        for (int l = 0; l < 4; l++) {
            float vf = bf[l] + w0f[l] * xm[l] + w1f[l] * x0[l] + w2f[l] * xp[l];
            float vb = bb[l] + w0b[l] * xp[l] + w1b[l] * x0[l] + w2b[l] * xm[l];
            f[l]  = __float2bfloat16_rn(vf);
            bw[l] = __float2bfloat16_rn(vb);
        }
        int off = (b * J_ + j) * E_ + e0;
        *(uint2*)&g_xcf[off] = *(uint2*)f;
        *(uint2*)&g_xcb[off] = *(uint2*)bw;
#pragma unroll
        for (int l = 0; l < 4; l++) { xm[l] = x0[l]; x0[l] = xp[l]; }
    }
}

// ---------------- K3b: TC GEMM xc @ [WB|WC|WD|Wi], double-buffered ------------
__global__ void __launch_bounds__(256) gemm_proj_tc() {
    __shared__ __align__(16) char smraw[33024];
    __nv_bfloat16* Asb = (__nv_bfloat16*)smraw;                      // [2][128*AP]
    __nv_bfloat16* Bsb = (__nv_bfloat16*)(smraw + 2 * 128 * AP * 2); // [2][32*BP]
    float (*sT)[129] = (float(*)[129])smraw;

    int dir = blockIdx.z;
    int bm = blockIdx.y * 128;
    int tid = threadIdx.x;
    int w = tid >> 5, lane = tid & 31;
    int wm = (w >> 1) * 32, wn = (w & 1) * 32;
    const __nv_bfloat16* Asrc = dir ? g_xcb : g_xcf;
    const __nv_bfloat16* Bsrc = g_wp + dir * (E_ * 64);

    float acc[2][4][4] = {};
    const int NK = E_ / 32;   // 12

    auto load_stage = [&](int s, int k0) {
#pragma unroll
        for (int it = 0; it < 2; it++) {
            int idx = tid + it * 256;
            int r = idx >> 2, seg = idx & 3;
            cp_async16(&Asb[s * 128 * AP + r * AP + seg * 8],
                       &Asrc[(bm + r) * E_ + k0 + seg * 8]);
        }
        {
            int r = tid >> 3, seg = tid & 7;
            cp_async16(&Bsb[s * 32 * BP + r * BP + seg * 8],
                       &Bsrc[(k0 + r) * 64 + seg * 8]);
        }
        CP_COMMIT();
    };

    load_stage(0, 0);
    for (int i = 0; i < NK; i++) {
        CP_WAIT0();
        __syncthreads();
        if (i + 1 < NK) load_stage((i + 1) & 1, (i + 1) * 32);
        mma_chunk(&Asb[(i & 1) * 128 * AP], &Bsb[(i & 1) * 32 * BP],
                  wm, wn, lane, acc);
        __syncthreads();
    }

    int gq = lane >> 2, tq = lane & 3;
#pragma unroll
    for (int i = 0; i < 2; i++) {
#pragma unroll
        for (int jj = 0; jj < 4; jj++) {
#pragma unroll
            for (int h = 0; h < 2; h++) {
                int rr = wm + i * 16 + gq + h * 8;
#pragma unroll
                for (int q = 0; q < 2; q++) {
                    int c = wn + jj * 8 + tq * 2 + q;
                    sT[c][rr] = acc[i][jj][h * 2 + q];
                }
            }
        }
    }
    __syncthreads();

    int b = bm >> 10;
    int j0 = bm & (J_ - 1);
    for (int i = tid; i < 64 * 128; i += 256) {
        int c = i >> 7, rr = i & 127;
        float v = sT[c][rr] + g_bp[dir * 64 + c];
        int j = j0 + rr;
        int pos = dir ? (J_ - 1 - j) : j;
        g_bcdu[(b * 128 + dir * 64 + c) * J_ + pos] = v;
    }
}

// ---------------- K4: fused bidirectional selective scan ----------------------
__global__ void scan2_kernel(const float* __restrict__ A_log) {
    int b = blockIdx.x >> 4;
    int n = blockIdx.x & 15;
    int t = threadIdx.x;
    float An = -softplusf(A_log[n]);
    float inv_den = 1.f / (An + 1e-6f);
    const float* base = g_bcdu + b * 128 * J_;

    __shared__ float sAcc[J_];
    __shared__ float sP[128], sS[128];

#pragma unroll
    for (int dir = 0; dir < 2; dir++) {
        int co = dir * 64;
        const float* Bt = base + (co + n) * J_;
        const float* Ct = base + (co + 16 + n) * J_;
        const float* Dr = base + (co + 32 + n) * J_;
        const float* Ut = base + (co + 48 + n) * J_;

        int j0 = t * 8;
        float hl[8], pp[8], cc[8];
        float P = 1.f, S = 0.f;
#pragma unroll
        for (int i = 0; i < 8; i++) {
            int j = j0 + i;
            float dt = softplusf(Dr[j]);
            float ab = expf(dt * An);
            float bu = (ab - 1.f) * inv_den * Bt[j] * Ut[j];
            S = ab * S + bu;
            P = P * ab;
            hl[i] = S; pp[i] = P; cc[i] = Ct[j];
        }
        float iP = P, iS = S;
        for (int off = 1; off < 128; off <<= 1) {
            sP[t] = iP; sS[t] = iS;
            __syncthreads();
            if (t >= off) {
                float qP = sP[t - off], qS = sS[t - off];
                iS = qS * iP + iS;
                iP = qP * iP;
            }
            __syncthreads();
        }
        sS[t] = iS;
        __syncthreads();
        float Hin = (t == 0) ? 0.f : sS[t - 1];
        __syncthreads();

#pragma unroll
        for (int i = 0; i < 8; i++) {
            int j = j0 + i;
            float h = hl[i] + pp[i] * Hin;
            float sc = h * cc[i];
            if (dir == 0) sAcc[j] = sc;
            else          sAcc[J_ - 1 - j] += sc;
        }
        __syncthreads();
    }

#pragma unroll
    for (int i = 0; i < 8; i++) {
        int pos = t * 8 + i;
        g_S[(b * J_ + pos) * N_ + n] = sAcc[pos];
    }
}

// ---------------- K5: readout + gate -> bf16 (8 outputs per thread) -----------
__global__ void __launch_bounds__(256) readout_kernel(const float* __restrict__ br) {
    const int NC = E_ / 8;            // 48 chunks per row
    int idx = blockIdx.x * blockDim.x + threadIdx.x;
    if (idx >= R_ * NC) return;
    int q = idx % NC;
    int r = idx / NC;
    int e0 = q * 8;

    // S row: 16 floats via 4x float4
    const float4* s4 = (const float4*)(g_S + r * N_);
    float sv[16];
#pragma unroll
    for (int i = 0; i < 4; i++) {
        float4 v = s4[i];
        sv[i * 4 + 0] = v.x; sv[i * 4 + 1] = v.y;
        sv[i * 4 + 2] = v.z; sv[i * 4 + 3] = v.w;
    }

    uint4 graw = *(const uint4*)&g_gateb[r * E_ + e0];
    const __nv_bfloat16* gv = (const __nv_bfloat16*)&graw;

    __nv_bfloat16 yv[8];
#pragma unroll
    for (int l = 0; l < 8; l++) {
        int e = e0 + l;
        uint4 w0 = *(const uint4*)&g_wrt[e * 16];
        uint4 w1 = *(const uint4*)&g_wrt[e * 16 + 8];
        const __nv_bfloat16* wh0 = (const __nv_bfloat16*)&w0;
        const __nv_bfloat16* wh1 = (const __nv_bfloat16*)&w1;
        float acc = 0.f;
#pragma unroll
        for (int n = 0; n < 8; n++) acc += sv[n] * __bfloat162float(wh0[n]);
#pragma unroll
        for (int n = 0; n < 8; n++) acc += sv[8 + n] * __bfloat162float(wh1[n]);
        yv[l] = __float2bfloat16_rn((acc + 2.f * br[e]) * __bfloat162float(gv[l]));
    }
    *(uint4*)&g_yb[r * E_ + e0] = *(uint4*)yv;
}

// ---------------- K6: TC GEMM y @ Wo + residual, double-buffered --------------
__global__ void __launch_bounds__(256) gemm_out_tc(const float* __restrict__ bo,
                                                   const float* __restrict__ tokens,
                                                   float* __restrict__ out) {
    __shared__ __align__(16) __nv_bfloat16 As[2][128 * AP];
    __shared__ __align__(16) __nv_bfloat16 Bs[2][32 * BP];
    int bm = blockIdx.y * 128;
    int bn = blockIdx.x * 64;
    int tid = threadIdx.x;
    int w = tid >> 5, lane = tid & 31;
    int wm = (w >> 1) * 32, wn = (w & 1) * 32;

    float acc[2][4][4] = {};
    const int NK = E_ / 32;   // 12

    auto load_stage = [&](int s, int k0) {
#pragma unroll
        for (int it = 0; it < 2; it++) {
            int idx = tid + it * 256;
            int r = idx >> 2, seg = idx & 3;
            cp_async16(&As[s][r * AP + seg * 8],
                       &g_yb[(bm + r) * E_ + k0 + seg * 8]);
        }
        {
            int r = tid >> 3, seg = tid & 7;
            cp_async16(&Bs[s][r * BP + seg * 8],
                       &g_wo[(k0 + r) * D_ + bn + seg * 8]);
        }
        CP_COMMIT();
    };

    load_stage(0, 0);
    for (int i = 0; i < NK; i++) {
        CP_WAIT0();
        __syncthreads();
        if (i + 1 < NK) load_stage((i + 1) & 1, (i + 1) * 32);
        mma_chunk(As[i & 1], Bs[i & 1], wm, wn, lane, acc);
        __syncthreads();
    }

    int gq = lane >> 2, tq = lane & 3;
#pragma unroll
    for (int i = 0; i < 2; i++) {
#pragma unroll
        for (int jj = 0; jj < 4; jj++) {
#pragma unroll
            for (int h = 0; h < 2; h++) {
                int r = bm + wm + i * 16 + gq + h * 8;
#pragma unroll
                for (int q = 0; q < 2; q++) {
                    int c = bn + wn + jj * 8 + tq * 2 + q;
                    out[r * D_ + c] = tokens[r * D_ + c]
                                    + acc[i][jj][h * 2 + q] + bo[c];
                }
            }
        }
    }
}

// ---------------- launcher ----------------------------------------------------
extern "C" void kernel_launch(void* const* d_in, const int* in_sizes, int n_in,
                              void* d_out, int out_size) {
    const float* tokens  = (const float*)d_in[0];
    const float* norm_g  = (const float*)d_in[1];
    const float* norm_b  = (const float*)d_in[2];
    const float* Wx      = (const float*)d_in[3];
    const float* bx      = (const float*)d_in[4];
    const float* Wz      = (const float*)d_in[5];
    const float* bz      = (const float*)d_in[6];
    const float* convf_w = (const float*)d_in[7];
    const float* convf_b = (const float*)d_in[8];
    const float* convb_w = (const float*)d_in[9];
    const float* convb_b = (const float*)d_in[10];
    const float* WBf = (const float*)d_in[11];
    const float* bBf = (const float*)d_in[12];
    const float* WCf = (const float*)d_in[13];
    const float* bCf = (const float*)d_in[14];
    const float* WDf = (const float*)d_in[15];
    const float* bDf = (const float*)d_in[16];
    const float* WBb = (const float*)d_in[17];
    const float* bBb = (const float*)d_in[18];
    const float* WCb = (const float*)d_in[19];
    const float* bCb = (const float*)d_in[20];
    const float* WDb = (const float*)d_in[21];
    const float* bDb = (const float*)d_in[22];
    const float* A_log = (const float*)d_in[23];
    const float* Wi  = (const float*)d_in[24];
    const float* bi  = (const float*)d_in[25];
    const float* Wr  = (const float*)d_in[26];
    const float* br  = (const float*)d_in[27];
    const float* Wo  = (const float*)d_in[28];
    const float* bo  = (const float*)d_in[29];
    float* out = (float*)d_out;

    const int nw = D_ * 2 * E_ + E_ * D_ + 2 * E_ * 64 + E_ * 16 + 128;
    wcvt_kernel<<<(nw + 255) / 256, 256>>>(Wx, Wz, Wo,
                                           WBf, WCf, WDf, WBb, WCb, WDb, Wi,
                                           bBf, bCf, bDf, bBb, bCb, bDb, bi, Wr);
    ln_kernel<<<R_ / 8, 256>>>(tokens, norm_g, norm_b);

    gemm_xz_tc<<<dim3(12, R_ / 128), 256>>>(bx, bz);

    conv3_kernel<<<(B_ * (J_ / 16) * (E_ / 4) + 255) / 256, 256>>>(
        convf_w, convf_b, convb_w, convb_b);

    gemm_proj_tc<<<dim3(1, R_ / 128, 2), 256>>>();

    scan2_kernel<<<B_ * N_, 128>>>(A_log);

    readout_kernel<<<(R_ * (E_ / 8) + 255) / 256, 256>>>(br);

    gemm_out_tc<<<dim3(3, R_ / 128), 256>>>(bo, tokens, out);
}